// round 1
// baseline (speedup 1.0000x reference)
#include <cuda_runtime.h>

#define B_SZ    2
#define Q_LEN   1024
#define K_LEN   2048
#define E_DIM   1024
#define N_HEADS 16
#define D_HEAD  64
#define ATT_SCALE 0.125f   // 1/sqrt(64)

// ---------------- scratch (static device globals; no allocation) ----------------
__device__ __align__(16) float g_q[B_SZ * N_HEADS * Q_LEN * D_HEAD];   // [B,H,Q,D]
__device__ __align__(16) float g_k[B_SZ * N_HEADS * K_LEN * D_HEAD];   // [B,H,K,D]
__device__ __align__(16) float g_v[B_SZ * N_HEADS * K_LEN * D_HEAD];   // [B,H,K,D]
__device__ __align__(16) float g_attn[B_SZ * Q_LEN * E_DIM];           // [B,Q,E]
__device__ __align__(16) float g_maskf[B_SZ * K_LEN];                  // 0 or -1e30

// ---------------- mask prep: sniff dtype of key_padding_mask, build float mask ----
// Hypotheses: u8 bool (1B), int32 (4B), float32 (4B), bf16 (2B). All encode 0/1.
//  - any byte > 1            -> floating (f32 or bf16)
//  - floating + any nonzero byte at idx%4==0 -> bf16 (f32 0.0/1.0 has byte0 == 0)
//  - integer  + any nonzero byte at idx%4!=0 -> u8 bool (int32 0/1 only sets byte0)
__global__ void mask_prep_kernel(const unsigned char* __restrict__ raw) {
    const int NM = B_SZ * K_LEN;
    int tid = threadIdx.x;
    int gt1 = 0, off = 0, low = 0;
    for (int i = tid; i < NM; i += 256) {
        unsigned char c = raw[i];
        if (c > 1) gt1 = 1;
        if ((i & 3) != 0 && c != 0) off = 1;
        if ((i & 3) == 0 && c != 0) low = 1;
    }
    int any_gt1 = __syncthreads_or(gt1);
    int any_off = __syncthreads_or(off);
    int any_low = __syncthreads_or(low);
    for (int i = tid; i < NM; i += 256) {
        bool mval;
        if (any_gt1) {
            if (any_low) mval = (((const unsigned short*)raw)[i] != 0);   // bf16
            else         mval = (((const float*)raw)[i] != 0.0f);         // f32
        } else {
            if (any_off) mval = (raw[i] != 0);                            // u8 bool
            else         mval = (((const int*)raw)[i] != 0);              // int32
        }
        g_maskf[i] = mval ? -1e30f : 0.0f;
    }
}

// ---------------- fp32 tiled GEMM:  C = A @ W^T + bias ----------------
// A: [M, 1024] row-major, W: [1024, 1024] row-major (N,K), bias: [1024]
// MODE 0: scatter into [B, H, S, D] layout (S = seq len), MODE 1: plain [M,N]
template <int MODE>
__global__ __launch_bounds__(256)
void gemm_bias_kernel(const float* __restrict__ A,
                      const float* __restrict__ W,
                      const float* __restrict__ bias,
                      float* __restrict__ C,
                      int M, int S) {
    const int N = 1024, Kd = 1024;
    __shared__ float As[8][128];
    __shared__ float Bs[8][128];

    int tid = threadIdx.x;
    int m0 = blockIdx.y * 128;
    int n0 = blockIdx.x * 128;
    int tr = tid >> 4;          // 0..15
    int tc = tid & 15;          // 0..15

    float acc[8][8];
#pragma unroll
    for (int i = 0; i < 8; i++)
#pragma unroll
        for (int j = 0; j < 8; j++) acc[i][j] = 0.0f;

    int lr = tid >> 1;              // 0..127
    int lc = (tid & 1) * 4;         // 0 or 4
    const float* Aptr = A + (size_t)(m0 + lr) * Kd + lc;
    const float* Wptr = W + (size_t)(n0 + lr) * Kd + lc;

    for (int kt = 0; kt < Kd; kt += 8) {
        float4 av = *((const float4*)(Aptr + kt));
        float4 wv = *((const float4*)(Wptr + kt));
        __syncthreads();
        As[lc + 0][lr] = av.x; As[lc + 1][lr] = av.y;
        As[lc + 2][lr] = av.z; As[lc + 3][lr] = av.w;
        Bs[lc + 0][lr] = wv.x; Bs[lc + 1][lr] = wv.y;
        Bs[lc + 2][lr] = wv.z; Bs[lc + 3][lr] = wv.w;
        __syncthreads();
#pragma unroll
        for (int kk = 0; kk < 8; kk++) {
            float a[8], b[8];
            *((float4*)&a[0]) = *((const float4*)&As[kk][tr * 8]);
            *((float4*)&a[4]) = *((const float4*)&As[kk][tr * 8 + 4]);
            *((float4*)&b[0]) = *((const float4*)&Bs[kk][tc * 8]);
            *((float4*)&b[4]) = *((const float4*)&Bs[kk][tc * 8 + 4]);
#pragma unroll
            for (int i = 0; i < 8; i++)
#pragma unroll
                for (int j = 0; j < 8; j++) acc[i][j] += a[i] * b[j];
        }
    }

#pragma unroll
    for (int i = 0; i < 8; i++) {
        int m = m0 + tr * 8 + i;
        int bidx = m / S;
        int sidx = m - bidx * S;
#pragma unroll
        for (int j = 0; j < 8; j += 4) {
            int n = n0 + tc * 8 + j;
            float4 r;
            r.x = acc[i][j + 0] + bias[n + 0];
            r.y = acc[i][j + 1] + bias[n + 1];
            r.z = acc[i][j + 2] + bias[n + 2];
            r.w = acc[i][j + 3] + bias[n + 3];
            if (MODE == 0) {
                int h = n >> 6;           // n / 64
                int dd = n & 63;          // n % 64
                float* dst = C + (((size_t)(bidx * N_HEADS + h)) * S + sidx) * D_HEAD + dd;
                *((float4*)dst) = r;
            } else {
                *((float4*)(C + (size_t)m * N + n)) = r;
            }
        }
    }
}

// ---------------- flash attention (fp32, online softmax) ----------------
// Block = one (b, h, 64-row Q tile). 256 threads: (qi, ki) = 16x16, 4x4 micro-tiles.
// Loops over 32 K-tiles of 64. Shared: Qs/Ks transposed [d][row], Vs/Ps [k][*].
__global__ __launch_bounds__(256)
void attention_kernel(const float* __restrict__ qg,
                      const float* __restrict__ kg,
                      const float* __restrict__ vg,
                      float* __restrict__ attn_out) {
    extern __shared__ float sm[];
    float* Qs = sm;                 // [64][68]  (d-major)
    float* Ks = Qs + 64 * 68;       // [64][68]  (d-major)
    float* Vs = Ks + 64 * 68;       // [64][68]  (k-major)
    float* Ps = Vs + 64 * 68;       // [64][68]  (k-major)
    float* ms = Ps + 64 * 68;       // [64]

    int qt = blockIdx.x;            // 0..15
    int h  = blockIdx.y;
    int b  = blockIdx.z;
    int tid = threadIdx.x;
    int qi = tid >> 4;              // 0..15
    int ki = tid & 15;              // 0..15

    const float* qbase = qg + (((size_t)(b * N_HEADS + h)) * Q_LEN + qt * 64) * D_HEAD;
    const float* kbase = kg + ((size_t)(b * N_HEADS + h)) * K_LEN * D_HEAD;
    const float* vbase = vg + ((size_t)(b * N_HEADS + h)) * K_LEN * D_HEAD;
    const float* mbase = g_maskf + b * K_LEN;

    // load Q tile, transposed into Qs[d][q]
    {
        int r = tid >> 2;
        int seg = (tid & 3) * 16;
        const float4* src = (const float4*)(qbase + r * D_HEAD + seg);
#pragma unroll
        for (int u = 0; u < 4; u++) {
            float4 v = src[u];
            int d0 = seg + u * 4;
            Qs[(d0 + 0) * 68 + r] = v.x;
            Qs[(d0 + 1) * 68 + r] = v.y;
            Qs[(d0 + 2) * 68 + r] = v.z;
            Qs[(d0 + 3) * 68 + r] = v.w;
        }
    }

    float m_i[4], l_i[4], o[4][4];
#pragma unroll
    for (int i = 0; i < 4; i++) {
        m_i[i] = -1e30f; l_i[i] = 0.0f;
#pragma unroll
        for (int j = 0; j < 4; j++) o[i][j] = 0.0f;
    }

    for (int kt = 0; kt < K_LEN / 64; kt++) {
        __syncthreads();            // previous tile fully consumed
        // load K (transposed), V (natural), mask slice
        {
            int r = tid >> 2;
            int seg = (tid & 3) * 16;
            const float4* ksrc = (const float4*)(kbase + (size_t)(kt * 64 + r) * D_HEAD + seg);
            const float4* vsrc = (const float4*)(vbase + (size_t)(kt * 64 + r) * D_HEAD + seg);
#pragma unroll
            for (int u = 0; u < 4; u++) {
                float4 kv = ksrc[u];
                int d0 = seg + u * 4;
                Ks[(d0 + 0) * 68 + r] = kv.x;
                Ks[(d0 + 1) * 68 + r] = kv.y;
                Ks[(d0 + 2) * 68 + r] = kv.z;
                Ks[(d0 + 3) * 68 + r] = kv.w;
                float4 vv = vsrc[u];
                *((float4*)(Vs + r * 68 + d0)) = vv;
            }
            if (tid < 64) ms[tid] = mbase[kt * 64 + tid];
        }
        __syncthreads();

        // S = Q K^T (64x64), each thread 4x4
        float s[4][4];
#pragma unroll
        for (int i = 0; i < 4; i++)
#pragma unroll
            for (int j = 0; j < 4; j++) s[i][j] = 0.0f;
        for (int d = 0; d < 64; d++) {
            float4 a = *((const float4*)(Qs + d * 68 + qi * 4));
            float4 bb = *((const float4*)(Ks + d * 68 + ki * 4));
            float av[4] = {a.x, a.y, a.z, a.w};
            float bv[4] = {bb.x, bb.y, bb.z, bb.w};
#pragma unroll
            for (int i = 0; i < 4; i++)
#pragma unroll
                for (int j = 0; j < 4; j++) s[i][j] += av[i] * bv[j];
        }
        float mk0 = ms[ki * 4 + 0], mk1 = ms[ki * 4 + 1];
        float mk2 = ms[ki * 4 + 2], mk3 = ms[ki * 4 + 3];
#pragma unroll
        for (int i = 0; i < 4; i++) {
            s[i][0] = s[i][0] * ATT_SCALE + mk0;
            s[i][1] = s[i][1] * ATT_SCALE + mk1;
            s[i][2] = s[i][2] * ATT_SCALE + mk2;
            s[i][3] = s[i][3] * ATT_SCALE + mk3;
        }

        // online softmax per row (16 threads own one row; butterfly within 16 lanes)
#pragma unroll
        for (int i = 0; i < 4; i++) {
            float mx = fmaxf(fmaxf(s[i][0], s[i][1]), fmaxf(s[i][2], s[i][3]));
#pragma unroll
            for (int off = 8; off >= 1; off >>= 1)
                mx = fmaxf(mx, __shfl_xor_sync(0xffffffffu, mx, off));
            float mnew = fmaxf(m_i[i], mx);
            float alpha = __expf(m_i[i] - mnew);
            m_i[i] = mnew;
            float rs = 0.0f;
#pragma unroll
            for (int j = 0; j < 4; j++) {
                s[i][j] = __expf(s[i][j] - mnew);
                rs += s[i][j];
            }
#pragma unroll
            for (int off = 8; off >= 1; off >>= 1)
                rs += __shfl_xor_sync(0xffffffffu, rs, off);
            l_i[i] = l_i[i] * alpha + rs;
#pragma unroll
            for (int j = 0; j < 4; j++) o[i][j] *= alpha;
        }

        // stage P transposed: Ps[k][q]
#pragma unroll
        for (int j = 0; j < 4; j++)
#pragma unroll
            for (int i = 0; i < 4; i++)
                Ps[(ki * 4 + j) * 68 + qi * 4 + i] = s[i][j];
        __syncthreads();

        // O += P @ V (thread = (qi, di=ki))
        for (int k = 0; k < 64; k++) {
            float4 a = *((const float4*)(Ps + k * 68 + qi * 4));
            float4 bb = *((const float4*)(Vs + k * 68 + ki * 4));
            float av[4] = {a.x, a.y, a.z, a.w};
            float bv[4] = {bb.x, bb.y, bb.z, bb.w};
#pragma unroll
            for (int i = 0; i < 4; i++)
#pragma unroll
                for (int j = 0; j < 4; j++) o[i][j] += av[i] * bv[j];
        }
    }

    // epilogue: normalize and write [B,Q,E] with heads merged
#pragma unroll
    for (int i = 0; i < 4; i++) {
        float inv = 1.0f / l_i[i];
        int q = qt * 64 + qi * 4 + i;
        float4 vv = make_float4(o[i][0] * inv, o[i][1] * inv, o[i][2] * inv, o[i][3] * inv);
        *((float4*)(attn_out + ((size_t)(b * Q_LEN + q)) * E_DIM + h * D_HEAD + ki * 4)) = vv;
    }
}

// ---------------- launch ----------------
extern "C" void kernel_launch(void* const* d_in, const int* in_sizes, int n_in,
                              void* d_out, int out_size) {
    const float* query = (const float*)d_in[0];
    const float* key   = (const float*)d_in[1];
    const float* value = (const float*)d_in[2];
    const unsigned char* mask = (const unsigned char*)d_in[3];
    const float* Wq = (const float*)d_in[4];
    const float* bq = (const float*)d_in[5];
    const float* Wk = (const float*)d_in[6];
    const float* bk = (const float*)d_in[7];
    const float* Wv = (const float*)d_in[8];
    const float* bv = (const float*)d_in[9];
    const float* Wo = (const float*)d_in[10];
    const float* bo = (const float*)d_in[11];
    float* out = (float*)d_out;

    float *qb, *kb, *vb, *ab;
    cudaGetSymbolAddress((void**)&qb, g_q);
    cudaGetSymbolAddress((void**)&kb, g_k);
    cudaGetSymbolAddress((void**)&vb, g_v);
    cudaGetSymbolAddress((void**)&ab, g_attn);

    mask_prep_kernel<<<1, 256>>>(mask);

    gemm_bias_kernel<0><<<dim3(8, 16), 256>>>(query, Wq, bq, qb, B_SZ * Q_LEN, Q_LEN);
    gemm_bias_kernel<0><<<dim3(8, 32), 256>>>(key,   Wk, bk, kb, B_SZ * K_LEN, K_LEN);
    gemm_bias_kernel<0><<<dim3(8, 32), 256>>>(value, Wv, bv, vb, B_SZ * K_LEN, K_LEN);

    size_t smem = (4 * 64 * 68 + 64) * sizeof(float);
    cudaFuncSetAttribute(attention_kernel,
                         cudaFuncAttributeMaxDynamicSharedMemorySize, (int)smem);
    attention_kernel<<<dim3(Q_LEN / 64, N_HEADS, B_SZ), 256, smem>>>(qb, kb, vb, ab);

    gemm_bias_kernel<1><<<dim3(8, 16), 256>>>(ab, Wo, bo, out, B_SZ * Q_LEN, Q_LEN);
}

// round 3
// speedup vs baseline: 1.4942x; 1.4942x over previous
#include <cuda_runtime.h>
#include <cuda_bf16.h>
#include <cstdint>

#define B_SZ    2
#define Q_LEN   1024
#define K_LEN   2048
#define E_DIM   1024
#define N_HEADS 16
#define D_HEAD  64
#define ATT_SCALE 0.125f   // 1/sqrt(64)

// ---------------- scratch (static device globals; no allocation) ----------------
__device__ __align__(16) float g_q[B_SZ * N_HEADS * Q_LEN * D_HEAD];   // [B,H,Q,D]
__device__ __align__(16) float g_k[B_SZ * N_HEADS * K_LEN * D_HEAD];   // [B,H,K,D]
__device__ __align__(16) float g_v[B_SZ * N_HEADS * K_LEN * D_HEAD];   // [B,H,K,D]
__device__ __align__(16) float g_attn[B_SZ * Q_LEN * E_DIM];           // [B,Q,E]
__device__ __align__(16) float g_maskf[B_SZ * K_LEN];                  // 0 or -1e30

// bf16 split buffers (hi/lo)
__device__ __align__(16) __nv_bfloat16 g_qh[B_SZ * Q_LEN * E_DIM];
__device__ __align__(16) __nv_bfloat16 g_ql[B_SZ * Q_LEN * E_DIM];
__device__ __align__(16) __nv_bfloat16 g_kh[B_SZ * K_LEN * E_DIM];
__device__ __align__(16) __nv_bfloat16 g_kl[B_SZ * K_LEN * E_DIM];
__device__ __align__(16) __nv_bfloat16 g_vh[B_SZ * K_LEN * E_DIM];
__device__ __align__(16) __nv_bfloat16 g_vl[B_SZ * K_LEN * E_DIM];
__device__ __align__(16) __nv_bfloat16 g_aoh[B_SZ * Q_LEN * E_DIM];
__device__ __align__(16) __nv_bfloat16 g_aol[B_SZ * Q_LEN * E_DIM];
__device__ __align__(16) __nv_bfloat16 g_wqh[E_DIM * E_DIM];
__device__ __align__(16) __nv_bfloat16 g_wql[E_DIM * E_DIM];
__device__ __align__(16) __nv_bfloat16 g_wkh[E_DIM * E_DIM];
__device__ __align__(16) __nv_bfloat16 g_wkl[E_DIM * E_DIM];
__device__ __align__(16) __nv_bfloat16 g_wvh[E_DIM * E_DIM];
__device__ __align__(16) __nv_bfloat16 g_wvl[E_DIM * E_DIM];
__device__ __align__(16) __nv_bfloat16 g_woh[E_DIM * E_DIM];
__device__ __align__(16) __nv_bfloat16 g_wol[E_DIM * E_DIM];

// ---------------- PTX helpers (portable sm_80+ only) ----------------
__device__ __forceinline__ uint32_t smem_u32(const void* p) {
    uint32_t a;
    asm("{ .reg .u64 t; cvta.to.shared.u64 t, %1; cvt.u32.u64 %0, t; }" : "=r"(a) : "l"(p));
    return a;
}
#define CP_ASYNC16(dst, src) \
    asm volatile("cp.async.cg.shared.global [%0], [%1], 16;" :: "r"(dst), "l"(src))
#define CP_COMMIT() asm volatile("cp.async.commit_group;" ::: "memory")
#define CP_WAIT(N)  asm volatile("cp.async.wait_group %0;" :: "n"(N) : "memory")

__device__ __forceinline__ void ldm_x4(uint32_t& r0, uint32_t& r1, uint32_t& r2,
                                       uint32_t& r3, uint32_t addr) {
    asm volatile("ldmatrix.sync.aligned.m8n8.x4.shared.b16 {%0,%1,%2,%3}, [%4];"
                 : "=r"(r0), "=r"(r1), "=r"(r2), "=r"(r3) : "r"(addr));
}
__device__ __forceinline__ void mma_bf16(float* c, const uint32_t* a,
                                         uint32_t b0, uint32_t b1) {
    asm volatile(
        "mma.sync.aligned.m16n8k16.row.col.f32.bf16.bf16.f32 "
        "{%0,%1,%2,%3}, {%4,%5,%6,%7}, {%8,%9}, {%0,%1,%2,%3};"
        : "+f"(c[0]), "+f"(c[1]), "+f"(c[2]), "+f"(c[3])
        : "r"(a[0]), "r"(a[1]), "r"(a[2]), "r"(a[3]), "r"(b0), "r"(b1));
}

// ---------------- mask prep (dtype sniffing) ----------------
__global__ void mask_prep_kernel(const unsigned char* __restrict__ raw) {
    const int NM = B_SZ * K_LEN;
    int tid = threadIdx.x;
    int gt1 = 0, off = 0, low = 0;
    for (int i = tid; i < NM; i += 256) {
        unsigned char c = raw[i];
        if (c > 1) gt1 = 1;
        if ((i & 3) != 0 && c != 0) off = 1;
        if ((i & 3) == 0 && c != 0) low = 1;
    }
    int any_gt1 = __syncthreads_or(gt1);
    int any_off = __syncthreads_or(off);
    int any_low = __syncthreads_or(low);
    for (int i = tid; i < NM; i += 256) {
        bool mval;
        if (any_gt1) {
            if (any_low) mval = (((const unsigned short*)raw)[i] != 0);
            else         mval = (((const float*)raw)[i] != 0.0f);
        } else {
            if (any_off) mval = (raw[i] != 0);
            else         mval = (((const int*)raw)[i] != 0);
        }
        g_maskf[i] = mval ? -1e30f : 0.0f;
    }
}

// ---------------- fp32 -> bf16 hi/lo split ----------------
__global__ __launch_bounds__(256)
void split_kernel(const float* __restrict__ x,
                  __nv_bfloat16* __restrict__ hi,
                  __nv_bfloat16* __restrict__ lo, int n4) {
    int i = blockIdx.x * 256 + threadIdx.x;
    int stride = gridDim.x * 256;
    for (; i < n4; i += stride) {
        float4 v = ((const float4*)x)[i];
        __nv_bfloat16 h0 = __float2bfloat16(v.x);
        __nv_bfloat16 h1 = __float2bfloat16(v.y);
        __nv_bfloat16 h2 = __float2bfloat16(v.z);
        __nv_bfloat16 h3 = __float2bfloat16(v.w);
        __nv_bfloat16 l0 = __float2bfloat16(v.x - __bfloat162float(h0));
        __nv_bfloat16 l1 = __float2bfloat16(v.y - __bfloat162float(h1));
        __nv_bfloat16 l2 = __float2bfloat16(v.z - __bfloat162float(h2));
        __nv_bfloat16 l3 = __float2bfloat16(v.w - __bfloat162float(h3));
        __nv_bfloat162 hp0; hp0.x = h0; hp0.y = h1;
        __nv_bfloat162 hp1; hp1.x = h2; hp1.y = h3;
        __nv_bfloat162 lp0; lp0.x = l0; lp0.y = l1;
        __nv_bfloat162 lp1; lp1.x = l2; lp1.y = l3;
        ((__nv_bfloat162*)hi)[i * 2 + 0] = hp0;
        ((__nv_bfloat162*)hi)[i * 2 + 1] = hp1;
        ((__nv_bfloat162*)lo)[i * 2 + 0] = lp0;
        ((__nv_bfloat162*)lo)[i * 2 + 1] = lp1;
    }
}

// ---------------- HMMA bf16-split GEMM: C = A @ W^T + bias ----------------
// A(hi/lo): [M,1024] bf16 K-major. W(hi/lo): [1024,1024] (N,K) K-major.
// Block tile 128x128, 8 warps (4m x 2n), warp tile 32x64, K-stage 32, double buffer.
// SMEM row stride 40 bf16 (80B): conflict-free ldmatrix (20r mod 32 distinct).
#define KSTAGE     32
#define ROWB       80                    // bytes per SMEM row
#define TILE_B     (128 * ROWB)          // 10240 B per (tile, half)
#define STAGE_B    (4 * TILE_B)          // Ah, Al, Wh, Wl = 40960 B
#define GEMM_SMEM  (2 * STAGE_B)         // 81920 B

template <int MODE>
__global__ __launch_bounds__(256)
void gemm_tc_kernel(const __nv_bfloat16* __restrict__ Ah,
                    const __nv_bfloat16* __restrict__ Al,
                    const __nv_bfloat16* __restrict__ Wh,
                    const __nv_bfloat16* __restrict__ Wl,
                    const float* __restrict__ bias,
                    float* __restrict__ C,
                    int M, int S) {
    extern __shared__ char sm[];
    uint32_t sbase = smem_u32(sm);

    int tid = threadIdx.x;
    int wid = tid >> 5;
    int lane = tid & 31;
    int m0 = blockIdx.y * 128;
    int n0 = blockIdx.x * 128;
    int warp_m = wid & 3;        // 0..3 (32 rows each)
    int warp_n = wid >> 2;       // 0..1 (64 cols each)

    const __nv_bfloat16* srcs[4] = {Ah, Al, Wh, Wl};

    // per-thread cp.async slots: per tile, 512 16B-chunks; tid covers 2 each.
    // chunk s: row = s>>2, c16 = s&3
    auto load_stage = [&](int buf, int kt) {
        uint32_t dst_base = sbase + buf * STAGE_B;
#pragma unroll
        for (int t = 0; t < 4; t++) {
            const __nv_bfloat16* src = srcs[t] + (size_t)(t < 2 ? m0 : n0) * E_DIM + kt * KSTAGE;
#pragma unroll
            for (int j = 0; j < 2; j++) {
                int s = tid + j * 256;
                int row = s >> 2;
                int c16 = s & 3;
                uint32_t dst = dst_base + t * TILE_B + row * ROWB + c16 * 16;
                CP_ASYNC16(dst, (const char*)(src + (size_t)row * E_DIM + c16 * 8));
            }
        }
    };

    // ldmatrix per-lane address components
    uint32_t a_off = (uint32_t)((warp_m * 32 + (lane & 15)) * ROWB + (lane >> 4) * 16);
    uint32_t b_off = (uint32_t)((warp_n * 64 + ((lane >> 4) * 8) + (lane & 7)) * ROWB
                                + ((lane >> 3) & 1) * 16);

    float acc[2][8][4];
#pragma unroll
    for (int i = 0; i < 2; i++)
#pragma unroll
        for (int j = 0; j < 8; j++)
#pragma unroll
            for (int k = 0; k < 4; k++) acc[i][j][k] = 0.0f;

    load_stage(0, 0);
    CP_COMMIT();

    int buf = 0;
    for (int kt = 0; kt < E_DIM / KSTAGE; kt++) {
        if (kt + 1 < E_DIM / KSTAGE) {
            load_stage(buf ^ 1, kt + 1);
            CP_COMMIT();
            CP_WAIT(1);
        } else {
            CP_WAIT(0);
        }
        __syncthreads();

        uint32_t stA = sbase + buf * STAGE_B;
        uint32_t stW = stA + 2 * TILE_B;
#pragma unroll
        for (int k16 = 0; k16 < 2; k16++) {
            uint32_t aH[2][4], aL[2][4], bH[4][4], bL[4][4];
#pragma unroll
            for (int mt = 0; mt < 2; mt++) {
                uint32_t ad = stA + a_off + mt * (16 * ROWB) + k16 * 32;
                ldm_x4(aH[mt][0], aH[mt][1], aH[mt][2], aH[mt][3], ad);
                ldm_x4(aL[mt][0], aL[mt][1], aL[mt][2], aL[mt][3], ad + TILE_B);
            }
#pragma unroll
            for (int p = 0; p < 4; p++) {
                uint32_t bd = stW + b_off + p * (16 * ROWB) + k16 * 32;
                ldm_x4(bH[p][0], bH[p][1], bH[p][2], bH[p][3], bd);
                ldm_x4(bL[p][0], bL[p][1], bL[p][2], bL[p][3], bd + TILE_B);
            }
            // pass 1: Ah * Wh
#pragma unroll
            for (int mt = 0; mt < 2; mt++)
#pragma unroll
                for (int nt = 0; nt < 8; nt++)
                    mma_bf16(acc[mt][nt], aH[mt], bH[nt >> 1][(nt & 1) * 2],
                             bH[nt >> 1][(nt & 1) * 2 + 1]);
            // pass 2: Ah * Wl
#pragma unroll
            for (int mt = 0; mt < 2; mt++)
#pragma unroll
                for (int nt = 0; nt < 8; nt++)
                    mma_bf16(acc[mt][nt], aH[mt], bL[nt >> 1][(nt & 1) * 2],
                             bL[nt >> 1][(nt & 1) * 2 + 1]);
            // pass 3: Al * Wh
#pragma unroll
            for (int mt = 0; mt < 2; mt++)
#pragma unroll
                for (int nt = 0; nt < 8; nt++)
                    mma_bf16(acc[mt][nt], aL[mt], bH[nt >> 1][(nt & 1) * 2],
                             bH[nt >> 1][(nt & 1) * 2 + 1]);
        }
        __syncthreads();
        buf ^= 1;
    }

    // epilogue
#pragma unroll
    for (int mt = 0; mt < 2; mt++) {
        int row_base = m0 + warp_m * 32 + mt * 16 + (lane >> 2);
#pragma unroll
        for (int half = 0; half < 2; half++) {
            int m = row_base + half * 8;
            int bidx = m / S;
            int sidx = m - bidx * S;
#pragma unroll
            for (int nt = 0; nt < 8; nt++) {
                int col = n0 + warp_n * 64 + nt * 8 + (lane & 3) * 2;
                float2 v;
                v.x = acc[mt][nt][half * 2 + 0] + bias[col + 0];
                v.y = acc[mt][nt][half * 2 + 1] + bias[col + 1];
                if (MODE == 0) {
                    int h = col >> 6;
                    int dd = col & 63;
                    float* dst = C + (((size_t)(bidx * N_HEADS + h)) * S + sidx) * D_HEAD + dd;
                    *((float2*)dst) = v;
                } else {
                    *((float2*)(C + (size_t)m * E_DIM + col)) = v;
                }
            }
        }
    }
}

// ---------------- flash attention (fp32 SIMT, unchanged) ----------------
__global__ __launch_bounds__(256)
void attention_kernel(const float* __restrict__ qg,
                      const float* __restrict__ kg,
                      const float* __restrict__ vg,
                      float* __restrict__ attn_out) {
    extern __shared__ float smf[];
    float* Qs = smf;
    float* Ks = Qs + 64 * 68;
    float* Vs = Ks + 64 * 68;
    float* Ps = Vs + 64 * 68;
    float* ms = Ps + 64 * 68;

    int qt = blockIdx.x;
    int h  = blockIdx.y;
    int b  = blockIdx.z;
    int tid = threadIdx.x;
    int qi = tid >> 4;
    int ki = tid & 15;

    const float* qbase = qg + (((size_t)(b * N_HEADS + h)) * Q_LEN + qt * 64) * D_HEAD;
    const float* kbase = kg + ((size_t)(b * N_HEADS + h)) * K_LEN * D_HEAD;
    const float* vbase = vg + ((size_t)(b * N_HEADS + h)) * K_LEN * D_HEAD;
    const float* mbase = g_maskf + b * K_LEN;

    {
        int r = tid >> 2;
        int seg = (tid & 3) * 16;
        const float4* src = (const float4*)(qbase + r * D_HEAD + seg);
#pragma unroll
        for (int u = 0; u < 4; u++) {
            float4 v = src[u];
            int d0 = seg + u * 4;
            Qs[(d0 + 0) * 68 + r] = v.x;
            Qs[(d0 + 1) * 68 + r] = v.y;
            Qs[(d0 + 2) * 68 + r] = v.z;
            Qs[(d0 + 3) * 68 + r] = v.w;
        }
    }

    float m_i[4], l_i[4], o[4][4];
#pragma unroll
    for (int i = 0; i < 4; i++) {
        m_i[i] = -1e30f; l_i[i] = 0.0f;
#pragma unroll
        for (int j = 0; j < 4; j++) o[i][j] = 0.0f;
    }

    for (int kt = 0; kt < K_LEN / 64; kt++) {
        __syncthreads();
        {
            int r = tid >> 2;
            int seg = (tid & 3) * 16;
            const float4* ksrc = (const float4*)(kbase + (size_t)(kt * 64 + r) * D_HEAD + seg);
            const float4* vsrc = (const float4*)(vbase + (size_t)(kt * 64 + r) * D_HEAD + seg);
#pragma unroll
            for (int u = 0; u < 4; u++) {
                float4 kv = ksrc[u];
                int d0 = seg + u * 4;
                Ks[(d0 + 0) * 68 + r] = kv.x;
                Ks[(d0 + 1) * 68 + r] = kv.y;
                Ks[(d0 + 2) * 68 + r] = kv.z;
                Ks[(d0 + 3) * 68 + r] = kv.w;
                float4 vv = vsrc[u];
                *((float4*)(Vs + r * 68 + d0)) = vv;
            }
            if (tid < 64) ms[tid] = mbase[kt * 64 + tid];
        }
        __syncthreads();

        float s[4][4];
#pragma unroll
        for (int i = 0; i < 4; i++)
#pragma unroll
            for (int j = 0; j < 4; j++) s[i][j] = 0.0f;
        for (int d = 0; d < 64; d++) {
            float4 a = *((const float4*)(Qs + d * 68 + qi * 4));
            float4 bb = *((const float4*)(Ks + d * 68 + ki * 4));
            float av[4] = {a.x, a.y, a.z, a.w};
            float bv[4] = {bb.x, bb.y, bb.z, bb.w};
#pragma unroll
            for (int i = 0; i < 4; i++)
#pragma unroll
                for (int j = 0; j < 4; j++) s[i][j] += av[i] * bv[j];
        }
        float mk0 = ms[ki * 4 + 0], mk1 = ms[ki * 4 + 1];
        float mk2 = ms[ki * 4 + 2], mk3 = ms[ki * 4 + 3];
#pragma unroll
        for (int i = 0; i < 4; i++) {
            s[i][0] = s[i][0] * ATT_SCALE + mk0;
            s[i][1] = s[i][1] * ATT_SCALE + mk1;
            s[i][2] = s[i][2] * ATT_SCALE + mk2;
            s[i][3] = s[i][3] * ATT_SCALE + mk3;
        }

#pragma unroll
        for (int i = 0; i < 4; i++) {
            float mx = fmaxf(fmaxf(s[i][0], s[i][1]), fmaxf(s[i][2], s[i][3]));
#pragma unroll
            for (int off = 8; off >= 1; off >>= 1)
                mx = fmaxf(mx, __shfl_xor_sync(0xffffffffu, mx, off));
            float mnew = fmaxf(m_i[i], mx);
            float alpha = __expf(m_i[i] - mnew);
            m_i[i] = mnew;
            float rs = 0.0f;
#pragma unroll
            for (int j = 0; j < 4; j++) {
                s[i][j] = __expf(s[i][j] - mnew);
                rs += s[i][j];
            }
#pragma unroll
            for (int off = 8; off >= 1; off >>= 1)
                rs += __shfl_xor_sync(0xffffffffu, rs, off);
            l_i[i] = l_i[i] * alpha + rs;
#pragma unroll
            for (int j = 0; j < 4; j++) o[i][j] *= alpha;
        }

#pragma unroll
        for (int j = 0; j < 4; j++)
#pragma unroll
            for (int i = 0; i < 4; i++)
                Ps[(ki * 4 + j) * 68 + qi * 4 + i] = s[i][j];
        __syncthreads();

        for (int k = 0; k < 64; k++) {
            float4 a = *((const float4*)(Ps + k * 68 + qi * 4));
            float4 bb = *((const float4*)(Vs + k * 68 + ki * 4));
            float av[4] = {a.x, a.y, a.z, a.w};
            float bv[4] = {bb.x, bb.y, bb.z, bb.w};
#pragma unroll
            for (int i = 0; i < 4; i++)
#pragma unroll
                for (int j = 0; j < 4; j++) o[i][j] += av[i] * bv[j];
        }
    }

#pragma unroll
    for (int i = 0; i < 4; i++) {
        float inv = 1.0f / l_i[i];
        int q = qt * 64 + qi * 4 + i;
        float4 vv = make_float4(o[i][0] * inv, o[i][1] * inv, o[i][2] * inv, o[i][3] * inv);
        *((float4*)(attn_out + ((size_t)(b * Q_LEN + q)) * E_DIM + h * D_HEAD + ki * 4)) = vv;
    }
}

// ---------------- launch ----------------
extern "C" void kernel_launch(void* const* d_in, const int* in_sizes, int n_in,
                              void* d_out, int out_size) {
    const float* query = (const float*)d_in[0];
    const float* key   = (const float*)d_in[1];
    const float* value = (const float*)d_in[2];
    const unsigned char* mask = (const unsigned char*)d_in[3];
    const float* Wq = (const float*)d_in[4];
    const float* bq = (const float*)d_in[5];
    const float* Wk = (const float*)d_in[6];
    const float* bk = (const float*)d_in[7];
    const float* Wv = (const float*)d_in[8];
    const float* bv = (const float*)d_in[9];
    const float* Wo = (const float*)d_in[10];
    const float* bo = (const float*)d_in[11];
    float* out = (float*)d_out;

    float *qb, *kb, *vb, *ab;
    cudaGetSymbolAddress((void**)&qb, g_q);
    cudaGetSymbolAddress((void**)&kb, g_k);
    cudaGetSymbolAddress((void**)&vb, g_v);
    cudaGetSymbolAddress((void**)&ab, g_attn);

    __nv_bfloat16 *qh, *ql, *kh, *kl, *vh, *vl, *aoh, *aol;
    __nv_bfloat16 *wqh, *wql, *wkh, *wkl, *wvh, *wvl, *woh, *wol;
    cudaGetSymbolAddress((void**)&qh, g_qh);   cudaGetSymbolAddress((void**)&ql, g_ql);
    cudaGetSymbolAddress((void**)&kh, g_kh);   cudaGetSymbolAddress((void**)&kl, g_kl);
    cudaGetSymbolAddress((void**)&vh, g_vh);   cudaGetSymbolAddress((void**)&vl, g_vl);
    cudaGetSymbolAddress((void**)&aoh, g_aoh); cudaGetSymbolAddress((void**)&aol, g_aol);
    cudaGetSymbolAddress((void**)&wqh, g_wqh); cudaGetSymbolAddress((void**)&wql, g_wql);
    cudaGetSymbolAddress((void**)&wkh, g_wkh); cudaGetSymbolAddress((void**)&wkl, g_wkl);
    cudaGetSymbolAddress((void**)&wvh, g_wvh); cudaGetSymbolAddress((void**)&wvl, g_wvl);
    cudaGetSymbolAddress((void**)&woh, g_woh); cudaGetSymbolAddress((void**)&wol, g_wol);

    mask_prep_kernel<<<1, 256>>>(mask);

    split_kernel<<<512, 256>>>(query, qh, ql, (B_SZ * Q_LEN * E_DIM) / 4);
    split_kernel<<<512, 256>>>(key,   kh, kl, (B_SZ * K_LEN * E_DIM) / 4);
    split_kernel<<<512, 256>>>(value, vh, vl, (B_SZ * K_LEN * E_DIM) / 4);
    split_kernel<<<256, 256>>>(Wq, wqh, wql, (E_DIM * E_DIM) / 4);
    split_kernel<<<256, 256>>>(Wk, wkh, wkl, (E_DIM * E_DIM) / 4);
    split_kernel<<<256, 256>>>(Wv, wvh, wvl, (E_DIM * E_DIM) / 4);
    split_kernel<<<256, 256>>>(Wo, woh, wol, (E_DIM * E_DIM) / 4);

    cudaFuncSetAttribute(gemm_tc_kernel<0>, cudaFuncAttributeMaxDynamicSharedMemorySize, GEMM_SMEM);
    cudaFuncSetAttribute(gemm_tc_kernel<1>, cudaFuncAttributeMaxDynamicSharedMemorySize, GEMM_SMEM);

    gemm_tc_kernel<0><<<dim3(8, 16), 256, GEMM_SMEM>>>(qh, ql, wqh, wql, bq, qb, B_SZ * Q_LEN, Q_LEN);
    gemm_tc_kernel<0><<<dim3(8, 32), 256, GEMM_SMEM>>>(kh, kl, wkh, wkl, bk, kb, B_SZ * K_LEN, K_LEN);
    gemm_tc_kernel<0><<<dim3(8, 32), 256, GEMM_SMEM>>>(vh, vl, wvh, wvl, bv, vb, B_SZ * K_LEN, K_LEN);

    size_t smem_att = (4 * 64 * 68 + 64) * sizeof(float);
    cudaFuncSetAttribute(attention_kernel,
                         cudaFuncAttributeMaxDynamicSharedMemorySize, (int)smem_att);
    attention_kernel<<<dim3(Q_LEN / 64, N_HEADS, B_SZ), 256, smem_att>>>(qb, kb, vb, ab);

    split_kernel<<<512, 256>>>(ab, aoh, aol, (B_SZ * Q_LEN * E_DIM) / 4);
    gemm_tc_kernel<1><<<dim3(8, 16), 256, GEMM_SMEM>>>(aoh, aol, woh, wol, bo, out, B_SZ * Q_LEN, Q_LEN);
}

// round 5
// speedup vs baseline: 2.7503x; 1.8407x over previous
#include <cuda_runtime.h>
#include <cuda_bf16.h>
#include <cstdint>

#define B_SZ    2
#define Q_LEN   1024
#define K_LEN   2048
#define E_DIM   1024
#define N_HEADS 16
#define D_HEAD  64
// 0.125 * log2(e)
#define SC_LOG2 0.1803368801111204f

// ---------------- scratch (static device globals; no allocation) ----------------
__device__ __align__(16) float g_maskf[B_SZ * K_LEN];                  // 0 or -1e30

// input splits (GEMM A operands)
__device__ __align__(16) __nv_bfloat16 g_qh[B_SZ * Q_LEN * E_DIM];
__device__ __align__(16) __nv_bfloat16 g_ql[B_SZ * Q_LEN * E_DIM];
__device__ __align__(16) __nv_bfloat16 g_kh[B_SZ * K_LEN * E_DIM];
__device__ __align__(16) __nv_bfloat16 g_kl[B_SZ * K_LEN * E_DIM];
__device__ __align__(16) __nv_bfloat16 g_vh[B_SZ * K_LEN * E_DIM];
__device__ __align__(16) __nv_bfloat16 g_vl[B_SZ * K_LEN * E_DIM];
// weight splits
__device__ __align__(16) __nv_bfloat16 g_wqh[E_DIM * E_DIM];
__device__ __align__(16) __nv_bfloat16 g_wql[E_DIM * E_DIM];
__device__ __align__(16) __nv_bfloat16 g_wkh[E_DIM * E_DIM];
__device__ __align__(16) __nv_bfloat16 g_wkl[E_DIM * E_DIM];
__device__ __align__(16) __nv_bfloat16 g_wvh[E_DIM * E_DIM];
__device__ __align__(16) __nv_bfloat16 g_wvl[E_DIM * E_DIM];
__device__ __align__(16) __nv_bfloat16 g_woh[E_DIM * E_DIM];
__device__ __align__(16) __nv_bfloat16 g_wol[E_DIM * E_DIM];
// projected q/k/v hi/lo in [B,H,S,D]
__device__ __align__(16) __nv_bfloat16 g_pqh[B_SZ * N_HEADS * Q_LEN * D_HEAD];
__device__ __align__(16) __nv_bfloat16 g_pql[B_SZ * N_HEADS * Q_LEN * D_HEAD];
__device__ __align__(16) __nv_bfloat16 g_pkh[B_SZ * N_HEADS * K_LEN * D_HEAD];
__device__ __align__(16) __nv_bfloat16 g_pkl[B_SZ * N_HEADS * K_LEN * D_HEAD];
__device__ __align__(16) __nv_bfloat16 g_pvh[B_SZ * N_HEADS * K_LEN * D_HEAD];
__device__ __align__(16) __nv_bfloat16 g_pvl[B_SZ * N_HEADS * K_LEN * D_HEAD];
// attention output hi/lo in [B*Q, E]
__device__ __align__(16) __nv_bfloat16 g_aoh[B_SZ * Q_LEN * E_DIM];
__device__ __align__(16) __nv_bfloat16 g_aol[B_SZ * Q_LEN * E_DIM];

// ---------------- PTX helpers (portable sm_80+ only) ----------------
__device__ __forceinline__ uint32_t smem_u32(const void* p) {
    uint32_t a;
    asm("{ .reg .u64 t; cvta.to.shared.u64 t, %1; cvt.u32.u64 %0, t; }" : "=r"(a) : "l"(p));
    return a;
}
#define CP_ASYNC16(dst, src) \
    asm volatile("cp.async.cg.shared.global [%0], [%1], 16;" :: "r"(dst), "l"(src))
#define CP_COMMIT() asm volatile("cp.async.commit_group;" ::: "memory")
#define CP_WAIT(N)  asm volatile("cp.async.wait_group %0;" :: "n"(N) : "memory")

__device__ __forceinline__ void ldm_x4(uint32_t& r0, uint32_t& r1, uint32_t& r2,
                                       uint32_t& r3, uint32_t addr) {
    asm volatile("ldmatrix.sync.aligned.m8n8.x4.shared.b16 {%0,%1,%2,%3}, [%4];"
                 : "=r"(r0), "=r"(r1), "=r"(r2), "=r"(r3) : "r"(addr));
}
__device__ __forceinline__ void ldm_x4t(uint32_t& r0, uint32_t& r1, uint32_t& r2,
                                        uint32_t& r3, uint32_t addr) {
    asm volatile("ldmatrix.sync.aligned.m8n8.x4.trans.shared.b16 {%0,%1,%2,%3}, [%4];"
                 : "=r"(r0), "=r"(r1), "=r"(r2), "=r"(r3) : "r"(addr));
}
__device__ __forceinline__ void mma_bf16(float* c, const uint32_t* a,
                                         uint32_t b0, uint32_t b1) {
    asm volatile(
        "mma.sync.aligned.m16n8k16.row.col.f32.bf16.bf16.f32 "
        "{%0,%1,%2,%3}, {%4,%5,%6,%7}, {%8,%9}, {%0,%1,%2,%3};"
        : "+f"(c[0]), "+f"(c[1]), "+f"(c[2]), "+f"(c[3])
        : "r"(a[0]), "r"(a[1]), "r"(a[2]), "r"(a[3]), "r"(b0), "r"(b1));
}
__device__ __forceinline__ float ex2f(float x) {
    float y; asm("ex2.approx.ftz.f32 %0, %1;" : "=f"(y) : "f"(x)); return y;
}
__device__ __forceinline__ uint32_t prmt7632(uint32_t a, uint32_t b) {
    uint32_t d; asm("prmt.b32 %0, %1, %2, 0x7632;" : "=r"(d) : "r"(a), "r"(b)); return d;
}
__device__ __forceinline__ uint32_t pack_bf16(float lo, float hi) {
    uint32_t d; asm("cvt.rn.bf16x2.f32 %0, %1, %2;" : "=r"(d) : "f"(hi), "f"(lo)); return d;
}

// ---------------- mask prep (dtype sniffing) ----------------
__global__ void mask_prep_kernel(const unsigned char* __restrict__ raw) {
    const int NM = B_SZ * K_LEN;
    int tid = threadIdx.x;
    int gt1 = 0, off = 0, low = 0;
    for (int i = tid; i < NM; i += 256) {
        unsigned char c = raw[i];
        if (c > 1) gt1 = 1;
        if ((i & 3) != 0 && c != 0) off = 1;
        if ((i & 3) == 0 && c != 0) low = 1;
    }
    int any_gt1 = __syncthreads_or(gt1);
    int any_off = __syncthreads_or(off);
    int any_low = __syncthreads_or(low);
    for (int i = tid; i < NM; i += 256) {
        bool mval;
        if (any_gt1) {
            if (any_low) mval = (((const unsigned short*)raw)[i] != 0);
            else         mval = (((const float*)raw)[i] != 0.0f);
        } else {
            if (any_off) mval = (raw[i] != 0);
            else         mval = (((const int*)raw)[i] != 0);
        }
        g_maskf[i] = mval ? -1e30f : 0.0f;
    }
}

// ---------------- fp32 -> bf16 hi/lo split ----------------
__global__ __launch_bounds__(256)
void split_kernel(const float* __restrict__ x,
                  __nv_bfloat16* __restrict__ hi,
                  __nv_bfloat16* __restrict__ lo, int n4) {
    int i = blockIdx.x * 256 + threadIdx.x;
    int stride = gridDim.x * 256;
    for (; i < n4; i += stride) {
        float4 v = ((const float4*)x)[i];
        __nv_bfloat16 h0 = __float2bfloat16(v.x);
        __nv_bfloat16 h1 = __float2bfloat16(v.y);
        __nv_bfloat16 h2 = __float2bfloat16(v.z);
        __nv_bfloat16 h3 = __float2bfloat16(v.w);
        __nv_bfloat16 l0 = __float2bfloat16(v.x - __bfloat162float(h0));
        __nv_bfloat16 l1 = __float2bfloat16(v.y - __bfloat162float(h1));
        __nv_bfloat16 l2 = __float2bfloat16(v.z - __bfloat162float(h2));
        __nv_bfloat16 l3 = __float2bfloat16(v.w - __bfloat162float(h3));
        __nv_bfloat162 hp0; hp0.x = h0; hp0.y = h1;
        __nv_bfloat162 hp1; hp1.x = h2; hp1.y = h3;
        __nv_bfloat162 lp0; lp0.x = l0; lp0.y = l1;
        __nv_bfloat162 lp1; lp1.x = l2; lp1.y = l3;
        ((__nv_bfloat162*)hi)[i * 2 + 0] = hp0;
        ((__nv_bfloat162*)hi)[i * 2 + 1] = hp1;
        ((__nv_bfloat162*)lo)[i * 2 + 0] = lp0;
        ((__nv_bfloat162*)lo)[i * 2 + 1] = lp1;
    }
}

// ---------------- HMMA bf16-split GEMM: C = A @ W^T + bias ----------------
// MODE 0: write bf16 hi/lo split scattered to [B,H,S,D]; MODE 1: fp32 [M,N].
#define KSTAGE     32
#define ROWB       80
#define TILE_B     (128 * ROWB)
#define STAGE_B    (4 * TILE_B)
#define GEMM_SMEM  (2 * STAGE_B)

template <int MODE>
__global__ __launch_bounds__(256)
void gemm_tc_kernel(const __nv_bfloat16* __restrict__ Ah,
                    const __nv_bfloat16* __restrict__ Al,
                    const __nv_bfloat16* __restrict__ Wh,
                    const __nv_bfloat16* __restrict__ Wl,
                    const float* __restrict__ bias,
                    float* __restrict__ C,
                    __nv_bfloat16* __restrict__ Ch,
                    __nv_bfloat16* __restrict__ Cl,
                    int M, int S) {
    extern __shared__ char sm[];
    uint32_t sbase = smem_u32(sm);

    int tid = threadIdx.x;
    int wid = tid >> 5;
    int lane = tid & 31;
    int m0 = blockIdx.y * 128;
    int n0 = blockIdx.x * 128;
    int warp_m = wid & 3;
    int warp_n = wid >> 2;

    const __nv_bfloat16* srcs[4] = {Ah, Al, Wh, Wl};

    auto load_stage = [&](int buf, int kt) {
        uint32_t dst_base = sbase + buf * STAGE_B;
#pragma unroll
        for (int t = 0; t < 4; t++) {
            const __nv_bfloat16* src = srcs[t] + (size_t)(t < 2 ? m0 : n0) * E_DIM + kt * KSTAGE;
#pragma unroll
            for (int j = 0; j < 2; j++) {
                int s = tid + j * 256;
                int row = s >> 2;
                int c16 = s & 3;
                uint32_t dst = dst_base + t * TILE_B + row * ROWB + c16 * 16;
                CP_ASYNC16(dst, (const char*)(src + (size_t)row * E_DIM + c16 * 8));
            }
        }
    };

    uint32_t a_off = (uint32_t)((warp_m * 32 + (lane & 15)) * ROWB + (lane >> 4) * 16);
    uint32_t b_off = (uint32_t)((warp_n * 64 + ((lane >> 4) * 8) + (lane & 7)) * ROWB
                                + ((lane >> 3) & 1) * 16);

    float acc[2][8][4];
#pragma unroll
    for (int i = 0; i < 2; i++)
#pragma unroll
        for (int j = 0; j < 8; j++)
#pragma unroll
            for (int k = 0; k < 4; k++) acc[i][j][k] = 0.0f;

    load_stage(0, 0);
    CP_COMMIT();

    int buf = 0;
    for (int kt = 0; kt < E_DIM / KSTAGE; kt++) {
        if (kt + 1 < E_DIM / KSTAGE) {
            load_stage(buf ^ 1, kt + 1);
            CP_COMMIT();
            CP_WAIT(1);
        } else {
            CP_WAIT(0);
        }
        __syncthreads();

        uint32_t stA = sbase + buf * STAGE_B;
        uint32_t stW = stA + 2 * TILE_B;
#pragma unroll
        for (int k16 = 0; k16 < 2; k16++) {
            uint32_t aH[2][4], aL[2][4], bH[4][4], bL[4][4];
#pragma unroll
            for (int mt = 0; mt < 2; mt++) {
                uint32_t ad = stA + a_off + mt * (16 * ROWB) + k16 * 32;
                ldm_x4(aH[mt][0], aH[mt][1], aH[mt][2], aH[mt][3], ad);
                ldm_x4(aL[mt][0], aL[mt][1], aL[mt][2], aL[mt][3], ad + TILE_B);
            }
#pragma unroll
            for (int p = 0; p < 4; p++) {
                uint32_t bd = stW + b_off + p * (16 * ROWB) + k16 * 32;
                ldm_x4(bH[p][0], bH[p][1], bH[p][2], bH[p][3], bd);
                ldm_x4(bL[p][0], bL[p][1], bL[p][2], bL[p][3], bd + TILE_B);
            }
#pragma unroll
            for (int mt = 0; mt < 2; mt++)
#pragma unroll
                for (int nt = 0; nt < 8; nt++)
                    mma_bf16(acc[mt][nt], aH[mt], bH[nt >> 1][(nt & 1) * 2],
                             bH[nt >> 1][(nt & 1) * 2 + 1]);
#pragma unroll
            for (int mt = 0; mt < 2; mt++)
#pragma unroll
                for (int nt = 0; nt < 8; nt++)
                    mma_bf16(acc[mt][nt], aH[mt], bL[nt >> 1][(nt & 1) * 2],
                             bL[nt >> 1][(nt & 1) * 2 + 1]);
#pragma unroll
            for (int mt = 0; mt < 2; mt++)
#pragma unroll
                for (int nt = 0; nt < 8; nt++)
                    mma_bf16(acc[mt][nt], aL[mt], bH[nt >> 1][(nt & 1) * 2],
                             bH[nt >> 1][(nt & 1) * 2 + 1]);
        }
        __syncthreads();
        buf ^= 1;
    }

#pragma unroll
    for (int mt = 0; mt < 2; mt++) {
        int row_base = m0 + warp_m * 32 + mt * 16 + (lane >> 2);
#pragma unroll
        for (int half = 0; half < 2; half++) {
            int m = row_base + half * 8;
            int bidx = m / S;
            int sidx = m - bidx * S;
#pragma unroll
            for (int nt = 0; nt < 8; nt++) {
                int col = n0 + warp_n * 64 + nt * 8 + (lane & 3) * 2;
                float vx = acc[mt][nt][half * 2 + 0] + bias[col + 0];
                float vy = acc[mt][nt][half * 2 + 1] + bias[col + 1];
                if (MODE == 0) {
                    int hh = col >> 6;
                    int dd = col & 63;
                    size_t off = (((size_t)(bidx * N_HEADS + hh)) * S + sidx) * D_HEAD + dd;
                    __nv_bfloat16 h0 = __float2bfloat16(vx);
                    __nv_bfloat16 h1 = __float2bfloat16(vy);
                    __nv_bfloat162 hp; hp.x = h0; hp.y = h1;
                    __nv_bfloat162 lp;
                    lp.x = __float2bfloat16(vx - __bfloat162float(h0));
                    lp.y = __float2bfloat16(vy - __bfloat162float(h1));
                    *(__nv_bfloat162*)(Ch + off) = hp;
                    *(__nv_bfloat162*)(Cl + off) = lp;
                } else {
                    float2 v; v.x = vx; v.y = vy;
                    *((float2*)(C + (size_t)m * E_DIM + col)) = v;
                }
            }
        }
    }
}

// ---------------- HMMA flash attention, bf16 hi/lo splits ----------------
#define AROW    144                 // bytes per 64-elem bf16 row (+16 pad)
#define Q_BYTES (128 * AROW)        // 18432 per half
#define KV_TILE (64 * AROW)         // 9216 per tensor-half
#define KV_STG  (4 * KV_TILE)       // Kh,Kl,Vh,Vl = 36864
#define AT_Q    0
#define AT_KV   (2 * Q_BYTES)       // 36864
#define AT_MS   (AT_KV + 2 * KV_STG)  // 110592
#define AT_SMEM (AT_MS + K_LEN * 4)   // 118784

__global__ __launch_bounds__(256, 1)
void attention_tc_kernel(const __nv_bfloat16* __restrict__ qh_g,
                         const __nv_bfloat16* __restrict__ ql_g,
                         const __nv_bfloat16* __restrict__ kh_g,
                         const __nv_bfloat16* __restrict__ kl_g,
                         const __nv_bfloat16* __restrict__ vh_g,
                         const __nv_bfloat16* __restrict__ vl_g,
                         __nv_bfloat16* __restrict__ oh_g,
                         __nv_bfloat16* __restrict__ ol_g) {
    extern __shared__ char sm[];
    uint32_t sbase = smem_u32(sm);
    int tid = threadIdx.x;
    int lane = tid & 31;
    int wid = tid >> 5;
    int qt = blockIdx.x;
    int h = blockIdx.y;
    int b = blockIdx.z;
    int bh = b * N_HEADS + h;

    // Q (hi/lo) + mask loads
    {
        const __nv_bfloat16* qs[2] = {qh_g, ql_g};
#pragma unroll
        for (int i = 0; i < 8; i++) {
            int c = tid + i * 256;
            int half = c >> 10, rem = c & 1023;
            int row = rem >> 3, seg = rem & 7;
            uint32_t dst = sbase + AT_Q + half * Q_BYTES + row * AROW + seg * 16;
            CP_ASYNC16(dst, qs[half] + ((size_t)(bh * Q_LEN + qt * 128 + row)) * 64 + seg * 8);
        }
        const float* msrc = g_maskf + b * K_LEN;
#pragma unroll
        for (int i = 0; i < 2; i++) {
            int c = tid + i * 256;
            CP_ASYNC16(sbase + AT_MS + c * 16, msrc + c * 4);
        }
    }
    CP_COMMIT();

    const __nv_bfloat16* kvs[4] = {kh_g, kl_g, vh_g, vl_g};
    auto load_kv = [&](int buf, int kt) {
        uint32_t SB = sbase + AT_KV + buf * KV_STG;
#pragma unroll
        for (int i = 0; i < 8; i++) {
            int c = tid + i * 256;
            int t = c >> 9, rem = c & 511;
            int row = rem >> 3, seg = rem & 7;
            CP_ASYNC16(SB + t * KV_TILE + row * AROW + seg * 16,
                       kvs[t] + ((size_t)(bh * K_LEN + kt * 64 + row)) * 64 + seg * 8);
        }
    };
    load_kv(0, 0);
    CP_COMMIT();
    CP_WAIT(1);            // Q + mask complete
    __syncthreads();

    // Q fragments (register resident for whole kernel)
    uint32_t qfh[4][4], qfl[4][4];
    {
        uint32_t qaddr = sbase + AT_Q + (wid * 16 + (lane & 15)) * AROW + (lane >> 4) * 16;
#pragma unroll
        for (int c2 = 0; c2 < 4; c2++) {
            ldm_x4(qfh[c2][0], qfh[c2][1], qfh[c2][2], qfh[c2][3], qaddr + c2 * 32);
            ldm_x4(qfl[c2][0], qfl[c2][1], qfl[c2][2], qfl[c2][3], qaddr + Q_BYTES + c2 * 32);
        }
    }

    float oacc[8][4];
#pragma unroll
    for (int i = 0; i < 8; i++)
#pragma unroll
        for (int j = 0; j < 4; j++) oacc[i][j] = 0.0f;
    float m0 = -50000.0f, m1 = -50000.0f, l0 = 0.0f, l1 = 0.0f;

    for (int kt = 0; kt < K_LEN / 64; kt++) {
        int buf = kt & 1;
        if (kt + 1 < K_LEN / 64) {
            load_kv(buf ^ 1, kt + 1);
            CP_COMMIT();
            CP_WAIT(1);
        } else {
            CP_WAIT(0);
        }
        __syncthreads();

        uint32_t SB = sbase + AT_KV + buf * KV_STG;

        // S = Q K^T (3-pass split), fp32 accum
        float sacc[8][4];
#pragma unroll
        for (int i = 0; i < 8; i++)
#pragma unroll
            for (int j = 0; j < 4; j++) sacc[i][j] = 0.0f;
#pragma unroll
        for (int c2 = 0; c2 < 4; c2++) {
            uint32_t khf[4][4], klf[4][4];
#pragma unroll
            for (int p = 0; p < 4; p++) {
                uint32_t kaddr = SB + (uint32_t)((p * 16 + (lane >> 4) * 8 + (lane & 7)) * AROW
                               + ((lane >> 3) & 1) * 16 + c2 * 32);
                ldm_x4(khf[p][0], khf[p][1], khf[p][2], khf[p][3], kaddr);
                ldm_x4(klf[p][0], klf[p][1], klf[p][2], klf[p][3], kaddr + KV_TILE);
            }
#pragma unroll
            for (int nt = 0; nt < 8; nt++) {
                uint32_t bh0 = khf[nt >> 1][(nt & 1) * 2], bh1 = khf[nt >> 1][(nt & 1) * 2 + 1];
                uint32_t bl0 = klf[nt >> 1][(nt & 1) * 2], bl1 = klf[nt >> 1][(nt & 1) * 2 + 1];
                mma_bf16(sacc[nt], qfh[c2], bh0, bh1);
                mma_bf16(sacc[nt], qfh[c2], bl0, bl1);
                mma_bf16(sacc[nt], qfl[c2], bh0, bh1);
            }
        }

        // scale to log2 domain + mask
        const float* msp = (const float*)(sm + AT_MS) + kt * 64;
#pragma unroll
        for (int nt = 0; nt < 8; nt++) {
            float2 mv = *(const float2*)(msp + nt * 8 + (lane & 3) * 2);
            sacc[nt][0] = fmaf(sacc[nt][0], SC_LOG2, mv.x);
            sacc[nt][1] = fmaf(sacc[nt][1], SC_LOG2, mv.y);
            sacc[nt][2] = fmaf(sacc[nt][2], SC_LOG2, mv.x);
            sacc[nt][3] = fmaf(sacc[nt][3], SC_LOG2, mv.y);
        }

        // online softmax (rows r0 = lane>>2, r1 = r0+8)
        float mx0 = sacc[0][0], mx1 = sacc[0][2];
#pragma unroll
        for (int nt = 0; nt < 8; nt++) {
            mx0 = fmaxf(mx0, fmaxf(sacc[nt][0], sacc[nt][1]));
            mx1 = fmaxf(mx1, fmaxf(sacc[nt][2], sacc[nt][3]));
        }
        mx0 = fmaxf(mx0, __shfl_xor_sync(0xffffffffu, mx0, 1));
        mx0 = fmaxf(mx0, __shfl_xor_sync(0xffffffffu, mx0, 2));
        mx1 = fmaxf(mx1, __shfl_xor_sync(0xffffffffu, mx1, 1));
        mx1 = fmaxf(mx1, __shfl_xor_sync(0xffffffffu, mx1, 2));
        float nm0 = fmaxf(m0, mx0), nm1 = fmaxf(m1, mx1);
        float a0 = ex2f(m0 - nm0), a1 = ex2f(m1 - nm1);
        m0 = nm0; m1 = nm1;

        float s0 = 0.0f, s1 = 0.0f;
#pragma unroll
        for (int nt = 0; nt < 8; nt++) {
            sacc[nt][0] = ex2f(sacc[nt][0] - nm0);
            sacc[nt][1] = ex2f(sacc[nt][1] - nm0);
            sacc[nt][2] = ex2f(sacc[nt][2] - nm1);
            sacc[nt][3] = ex2f(sacc[nt][3] - nm1);
            s0 += sacc[nt][0] + sacc[nt][1];
            s1 += sacc[nt][2] + sacc[nt][3];
        }
        s0 += __shfl_xor_sync(0xffffffffu, s0, 1);
        s0 += __shfl_xor_sync(0xffffffffu, s0, 2);
        s1 += __shfl_xor_sync(0xffffffffu, s1, 1);
        s1 += __shfl_xor_sync(0xffffffffu, s1, 2);
        l0 = l0 * a0 + s0;
        l1 = l1 * a1 + s1;
#pragma unroll
        for (int nf = 0; nf < 8; nf++) {
            oacc[nf][0] *= a0; oacc[nf][1] *= a0;
            oacc[nf][2] *= a1; oacc[nf][3] *= a1;
        }

        // O += P V (3-pass split); P split via truncation + residual
#pragma unroll
        for (int j = 0; j < 4; j++) {
            uint32_t ph[4], pl[4];
#pragma unroll
            for (int half = 0; half < 2; half++) {
                int f = 2 * j + half;
                uint32_t u0 = __float_as_uint(sacc[f][0]);
                uint32_t u1 = __float_as_uint(sacc[f][1]);
                uint32_t u2 = __float_as_uint(sacc[f][2]);
                uint32_t u3 = __float_as_uint(sacc[f][3]);
                // a0 = (r0, k 0-7), a1 = (r1, k 0-7), a2 = (r0, k 8-15), a3 = (r1, k 8-15)
                ph[half ? 2 : 0] = prmt7632(u0, u1);
                ph[half ? 3 : 1] = prmt7632(u2, u3);
                float q0 = sacc[f][0] - __uint_as_float(u0 & 0xFFFF0000u);
                float q1 = sacc[f][1] - __uint_as_float(u1 & 0xFFFF0000u);
                float q2 = sacc[f][2] - __uint_as_float(u2 & 0xFFFF0000u);
                float q3 = sacc[f][3] - __uint_as_float(u3 & 0xFFFF0000u);
                pl[half ? 2 : 0] = pack_bf16(q0, q1);
                pl[half ? 3 : 1] = pack_bf16(q2, q3);
            }
#pragma unroll
            for (int q2b = 0; q2b < 4; q2b++) {
                uint32_t vhf[4], vlf[4];
                uint32_t vaddr = SB + 2 * KV_TILE
                               + (uint32_t)((j * 16 + (lane & 15)) * AROW
                               + q2b * 32 + (lane >> 4) * 16);
                ldm_x4t(vhf[0], vhf[1], vhf[2], vhf[3], vaddr);
                ldm_x4t(vlf[0], vlf[1], vlf[2], vlf[3], vaddr + KV_TILE);
                mma_bf16(oacc[q2b * 2 + 0], ph, vhf[0], vhf[1]);
                mma_bf16(oacc[q2b * 2 + 0], ph, vlf[0], vlf[1]);
                mma_bf16(oacc[q2b * 2 + 0], pl, vhf[0], vhf[1]);
                mma_bf16(oacc[q2b * 2 + 1], ph, vhf[2], vhf[3]);
                mma_bf16(oacc[q2b * 2 + 1], ph, vlf[2], vlf[3]);
                mma_bf16(oacc[q2b * 2 + 1], pl, vhf[2], vhf[3]);
            }
        }
        __syncthreads();
    }

    // epilogue: normalize, split to bf16 hi/lo, write [B*Q, E]
    float inv0 = 1.0f / l0, inv1 = 1.0f / l1;
    int qrow = qt * 128 + wid * 16 + (lane >> 2);
    size_t row0 = (size_t)b * Q_LEN + qrow;
    size_t row1 = row0 + 8;
#pragma unroll
    for (int nf = 0; nf < 8; nf++) {
        int col = h * 64 + nf * 8 + (lane & 3) * 2;
        {
            float vx = oacc[nf][0] * inv0, vy = oacc[nf][1] * inv0;
            __nv_bfloat16 h0 = __float2bfloat16(vx), h1 = __float2bfloat16(vy);
            __nv_bfloat162 hp; hp.x = h0; hp.y = h1;
            __nv_bfloat162 lp;
            lp.x = __float2bfloat16(vx - __bfloat162float(h0));
            lp.y = __float2bfloat16(vy - __bfloat162float(h1));
            *(__nv_bfloat162*)(oh_g + row0 * E_DIM + col) = hp;
            *(__nv_bfloat162*)(ol_g + row0 * E_DIM + col) = lp;
        }
        {
            float vx = oacc[nf][2] * inv1, vy = oacc[nf][3] * inv1;
            __nv_bfloat16 h0 = __float2bfloat16(vx), h1 = __float2bfloat16(vy);
            __nv_bfloat162 hp; hp.x = h0; hp.y = h1;
            __nv_bfloat162 lp;
            lp.x = __float2bfloat16(vx - __bfloat162float(h0));
            lp.y = __float2bfloat16(vy - __bfloat162float(h1));
            *(__nv_bfloat162*)(oh_g + row1 * E_DIM + col) = hp;
            *(__nv_bfloat162*)(ol_g + row1 * E_DIM + col) = lp;
        }
    }
}

// ---------------- launch ----------------
extern "C" void kernel_launch(void* const* d_in, const int* in_sizes, int n_in,
                              void* d_out, int out_size) {
    const float* query = (const float*)d_in[0];
    const float* key   = (const float*)d_in[1];
    const float* value = (const float*)d_in[2];
    const unsigned char* mask = (const unsigned char*)d_in[3];
    const float* Wq = (const float*)d_in[4];
    const float* bq = (const float*)d_in[5];
    const float* Wk = (const float*)d_in[6];
    const float* bk = (const float*)d_in[7];
    const float* Wv = (const float*)d_in[8];
    const float* bv = (const float*)d_in[9];
    const float* Wo = (const float*)d_in[10];
    const float* bo = (const float*)d_in[11];
    float* out = (float*)d_out;

    __nv_bfloat16 *qh, *ql, *kh, *kl, *vh, *vl, *aoh, *aol;
    __nv_bfloat16 *wqh, *wql, *wkh, *wkl, *wvh, *wvl, *woh, *wol;
    __nv_bfloat16 *pqh, *pql, *pkh, *pkl, *pvh, *pvl;
    cudaGetSymbolAddress((void**)&qh, g_qh);   cudaGetSymbolAddress((void**)&ql, g_ql);
    cudaGetSymbolAddress((void**)&kh, g_kh);   cudaGetSymbolAddress((void**)&kl, g_kl);
    cudaGetSymbolAddress((void**)&vh, g_vh);   cudaGetSymbolAddress((void**)&vl, g_vl);
    cudaGetSymbolAddress((void**)&aoh, g_aoh); cudaGetSymbolAddress((void**)&aol, g_aol);
    cudaGetSymbolAddress((void**)&wqh, g_wqh); cudaGetSymbolAddress((void**)&wql, g_wql);
    cudaGetSymbolAddress((void**)&wkh, g_wkh); cudaGetSymbolAddress((void**)&wkl, g_wkl);
    cudaGetSymbolAddress((void**)&wvh, g_wvh); cudaGetSymbolAddress((void**)&wvl, g_wvl);
    cudaGetSymbolAddress((void**)&woh, g_woh); cudaGetSymbolAddress((void**)&wol, g_wol);
    cudaGetSymbolAddress((void**)&pqh, g_pqh); cudaGetSymbolAddress((void**)&pql, g_pql);
    cudaGetSymbolAddress((void**)&pkh, g_pkh); cudaGetSymbolAddress((void**)&pkl, g_pkl);
    cudaGetSymbolAddress((void**)&pvh, g_pvh); cudaGetSymbolAddress((void**)&pvl, g_pvl);

    mask_prep_kernel<<<1, 256>>>(mask);

    split_kernel<<<512, 256>>>(query, qh, ql, (B_SZ * Q_LEN * E_DIM) / 4);
    split_kernel<<<512, 256>>>(key,   kh, kl, (B_SZ * K_LEN * E_DIM) / 4);
    split_kernel<<<512, 256>>>(value, vh, vl, (B_SZ * K_LEN * E_DIM) / 4);
    split_kernel<<<256, 256>>>(Wq, wqh, wql, (E_DIM * E_DIM) / 4);
    split_kernel<<<256, 256>>>(Wk, wkh, wkl, (E_DIM * E_DIM) / 4);
    split_kernel<<<256, 256>>>(Wv, wvh, wvl, (E_DIM * E_DIM) / 4);
    split_kernel<<<256, 256>>>(Wo, woh, wol, (E_DIM * E_DIM) / 4);

    cudaFuncSetAttribute(gemm_tc_kernel<0>, cudaFuncAttributeMaxDynamicSharedMemorySize, GEMM_SMEM);
    cudaFuncSetAttribute(gemm_tc_kernel<1>, cudaFuncAttributeMaxDynamicSharedMemorySize, GEMM_SMEM);

    gemm_tc_kernel<0><<<dim3(8, 16), 256, GEMM_SMEM>>>(qh, ql, wqh, wql, bq,
                                                       nullptr, pqh, pql, B_SZ * Q_LEN, Q_LEN);
    gemm_tc_kernel<0><<<dim3(8, 32), 256, GEMM_SMEM>>>(kh, kl, wkh, wkl, bk,
                                                       nullptr, pkh, pkl, B_SZ * K_LEN, K_LEN);
    gemm_tc_kernel<0><<<dim3(8, 32), 256, GEMM_SMEM>>>(vh, vl, wvh, wvl, bv,
                                                       nullptr, pvh, pvl, B_SZ * K_LEN, K_LEN);

    cudaFuncSetAttribute(attention_tc_kernel, cudaFuncAttributeMaxDynamicSharedMemorySize, AT_SMEM);
    attention_tc_kernel<<<dim3(Q_LEN / 128, N_HEADS, B_SZ), 256, AT_SMEM>>>(
        pqh, pql, pkh, pkl, pvh, pvl, aoh, aol);

    gemm_tc_kernel<1><<<dim3(8, 16), 256, GEMM_SMEM>>>(aoh, aol, woh, wol, bo,
                                                       out, nullptr, nullptr, B_SZ * Q_LEN, Q_LEN);
}

// round 6
// speedup vs baseline: 4.1231x; 1.4992x over previous
#include <cuda_runtime.h>
#include <cuda_fp16.h>
#include <cstdint>

#define B_SZ    2
#define Q_LEN   1024
#define K_LEN   2048
#define E_DIM   1024
#define N_HEADS 16
#define D_HEAD  64
// 0.125 * log2(e)
#define SC_LOG2 0.1803368801111204f

// ---------------- scratch (static device globals; no allocation) ----------------
__device__ __align__(16) float g_maskf[B_SZ * K_LEN];                  // 0 or -1e30

// input splits (GEMM A operands, fp16 hi/lo)
__device__ __align__(16) __half g_qh[B_SZ * Q_LEN * E_DIM];
__device__ __align__(16) __half g_ql[B_SZ * Q_LEN * E_DIM];
__device__ __align__(16) __half g_kh[B_SZ * K_LEN * E_DIM];
__device__ __align__(16) __half g_kl[B_SZ * K_LEN * E_DIM];
__device__ __align__(16) __half g_vh[B_SZ * K_LEN * E_DIM];
__device__ __align__(16) __half g_vl[B_SZ * K_LEN * E_DIM];
// weights: single fp16
__device__ __align__(16) __half g_wq16[E_DIM * E_DIM];
__device__ __align__(16) __half g_wk16[E_DIM * E_DIM];
__device__ __align__(16) __half g_wv16[E_DIM * E_DIM];
__device__ __align__(16) __half g_wo16[E_DIM * E_DIM];
// projected q hi/lo, k/v single, in [B,H,S,D]
__device__ __align__(16) __half g_pqh[B_SZ * N_HEADS * Q_LEN * D_HEAD];
__device__ __align__(16) __half g_pql[B_SZ * N_HEADS * Q_LEN * D_HEAD];
__device__ __align__(16) __half g_pk16[B_SZ * N_HEADS * K_LEN * D_HEAD];
__device__ __align__(16) __half g_pv16[B_SZ * N_HEADS * K_LEN * D_HEAD];
// attention output hi/lo in [B*Q, E]
__device__ __align__(16) __half g_aoh[B_SZ * Q_LEN * E_DIM];
__device__ __align__(16) __half g_aol[B_SZ * Q_LEN * E_DIM];

// ---------------- PTX helpers (portable sm_80+ only) ----------------
__device__ __forceinline__ uint32_t smem_u32(const void* p) {
    uint32_t a;
    asm("{ .reg .u64 t; cvta.to.shared.u64 t, %1; cvt.u32.u64 %0, t; }" : "=r"(a) : "l"(p));
    return a;
}
#define CP_ASYNC16(dst, src) \
    asm volatile("cp.async.cg.shared.global [%0], [%1], 16;" :: "r"(dst), "l"(src))
#define CP_COMMIT() asm volatile("cp.async.commit_group;" ::: "memory")
#define CP_WAIT(N)  asm volatile("cp.async.wait_group %0;" :: "n"(N) : "memory")

__device__ __forceinline__ void ldm_x4(uint32_t& r0, uint32_t& r1, uint32_t& r2,
                                       uint32_t& r3, uint32_t addr) {
    asm volatile("ldmatrix.sync.aligned.m8n8.x4.shared.b16 {%0,%1,%2,%3}, [%4];"
                 : "=r"(r0), "=r"(r1), "=r"(r2), "=r"(r3) : "r"(addr));
}
__device__ __forceinline__ void ldm_x4t(uint32_t& r0, uint32_t& r1, uint32_t& r2,
                                        uint32_t& r3, uint32_t addr) {
    asm volatile("ldmatrix.sync.aligned.m8n8.x4.trans.shared.b16 {%0,%1,%2,%3}, [%4];"
                 : "=r"(r0), "=r"(r1), "=r"(r2), "=r"(r3) : "r"(addr));
}
__device__ __forceinline__ void mma_f16(float* c, const uint32_t* a,
                                        uint32_t b0, uint32_t b1) {
    asm volatile(
        "mma.sync.aligned.m16n8k16.row.col.f32.f16.f16.f32 "
        "{%0,%1,%2,%3}, {%4,%5,%6,%7}, {%8,%9}, {%0,%1,%2,%3};"
        : "+f"(c[0]), "+f"(c[1]), "+f"(c[2]), "+f"(c[3])
        : "r"(a[0]), "r"(a[1]), "r"(a[2]), "r"(a[3]), "r"(b0), "r"(b1));
}
__device__ __forceinline__ float ex2f(float x) {
    float y; asm("ex2.approx.ftz.f32 %0, %1;" : "=f"(y) : "f"(x)); return y;
}

// ---------------- mask prep (dtype sniffing) ----------------
__global__ void mask_prep_kernel(const unsigned char* __restrict__ raw) {
    const int NM = B_SZ * K_LEN;
    int tid = threadIdx.x;
    int gt1 = 0, off = 0, low = 0;
    for (int i = tid; i < NM; i += 256) {
        unsigned char c = raw[i];
        if (c > 1) gt1 = 1;
        if ((i & 3) != 0 && c != 0) off = 1;
        if ((i & 3) == 0 && c != 0) low = 1;
    }
    int any_gt1 = __syncthreads_or(gt1);
    int any_off = __syncthreads_or(off);
    int any_low = __syncthreads_or(low);
    for (int i = tid; i < NM; i += 256) {
        bool mval;
        if (any_gt1) {
            if (any_low) mval = (((const unsigned short*)raw)[i] != 0);
            else         mval = (((const float*)raw)[i] != 0.0f);
        } else {
            if (any_off) mval = (raw[i] != 0);
            else         mval = (((const int*)raw)[i] != 0);
        }
        g_maskf[i] = mval ? -1e30f : 0.0f;
    }
}

// ---------------- fp32 -> fp16 hi/lo split ----------------
__global__ __launch_bounds__(256)
void split16_kernel(const float* __restrict__ x,
                    __half* __restrict__ hi,
                    __half* __restrict__ lo, int n4) {
    int i = blockIdx.x * 256 + threadIdx.x;
    int stride = gridDim.x * 256;
    for (; i < n4; i += stride) {
        float4 v = ((const float4*)x)[i];
        __half2 h0 = __floats2half2_rn(v.x, v.y);
        __half2 h1 = __floats2half2_rn(v.z, v.w);
        float2 f0 = __half22float2(h0);
        float2 f1 = __half22float2(h1);
        __half2 l0 = __floats2half2_rn(v.x - f0.x, v.y - f0.y);
        __half2 l1 = __floats2half2_rn(v.z - f1.x, v.w - f1.y);
        ((__half2*)hi)[i * 2 + 0] = h0;
        ((__half2*)hi)[i * 2 + 1] = h1;
        ((__half2*)lo)[i * 2 + 0] = l0;
        ((__half2*)lo)[i * 2 + 1] = l1;
    }
}

// ---------------- fp32 -> fp16 convert (4 weight matrices, fused) --------------
__global__ __launch_bounds__(256)
void conv16_kernel(const float* __restrict__ w0, const float* __restrict__ w1,
                   const float* __restrict__ w2, const float* __restrict__ w3,
                   __half* __restrict__ o0, __half* __restrict__ o1,
                   __half* __restrict__ o2, __half* __restrict__ o3, int n4) {
    const float* srcs[4] = {w0, w1, w2, w3};
    __half* dsts[4] = {o0, o1, o2, o3};
    const float* x = srcs[blockIdx.y];
    __half* o = dsts[blockIdx.y];
    int i = blockIdx.x * 256 + threadIdx.x;
    int stride = gridDim.x * 256;
    for (; i < n4; i += stride) {
        float4 v = ((const float4*)x)[i];
        ((__half2*)o)[i * 2 + 0] = __floats2half2_rn(v.x, v.y);
        ((__half2*)o)[i * 2 + 1] = __floats2half2_rn(v.z, v.w);
    }
}

// ---------------- HMMA fp16 2-pass GEMM: C = A @ W^T + bias ----------------
// A split (Ah, Al) fp16, W single fp16. C = Ah*W + Al*W.
// MODE 0: split fp16 out scattered [B,H,S,D]; MODE 1: single fp16 out scattered;
// MODE 2: fp32 [M,N].
#define KSTAGE     32
#define ROWB       80
#define TILE_B     (128 * ROWB)
#define STAGE_B    (3 * TILE_B)          // Ah, Al, W
#define GEMM_SMEM  (2 * STAGE_B)         // 61440

template <int MODE>
__global__ __launch_bounds__(256)
void gemm_tc_kernel(const __half* __restrict__ Ah,
                    const __half* __restrict__ Al,
                    const __half* __restrict__ W16,
                    const float* __restrict__ bias,
                    float* __restrict__ C,
                    __half* __restrict__ Ch,
                    __half* __restrict__ Cl,
                    int M, int S) {
    extern __shared__ char sm[];
    uint32_t sbase = smem_u32(sm);

    int tid = threadIdx.x;
    int wid = tid >> 5;
    int lane = tid & 31;
    int m0 = blockIdx.y * 128;
    int n0 = blockIdx.x * 128;
    int warp_m = wid & 3;
    int warp_n = wid >> 2;

    const __half* srcs[3] = {Ah, Al, W16};

    auto load_stage = [&](int buf, int kt) {
        uint32_t dst_base = sbase + buf * STAGE_B;
#pragma unroll
        for (int t = 0; t < 3; t++) {
            const __half* src = srcs[t] + (size_t)(t < 2 ? m0 : n0) * E_DIM + kt * KSTAGE;
#pragma unroll
            for (int j = 0; j < 2; j++) {
                int s = tid + j * 256;
                int row = s >> 2;
                int c16 = s & 3;
                uint32_t dst = dst_base + t * TILE_B + row * ROWB + c16 * 16;
                CP_ASYNC16(dst, (const char*)(src + (size_t)row * E_DIM + c16 * 8));
            }
        }
    };

    uint32_t a_off = (uint32_t)((warp_m * 32 + (lane & 15)) * ROWB + (lane >> 4) * 16);
    uint32_t b_off = (uint32_t)((warp_n * 64 + ((lane >> 4) * 8) + (lane & 7)) * ROWB
                                + ((lane >> 3) & 1) * 16);

    float acc[2][8][4];
#pragma unroll
    for (int i = 0; i < 2; i++)
#pragma unroll
        for (int j = 0; j < 8; j++)
#pragma unroll
            for (int k = 0; k < 4; k++) acc[i][j][k] = 0.0f;

    load_stage(0, 0);
    CP_COMMIT();

    int buf = 0;
    for (int kt = 0; kt < E_DIM / KSTAGE; kt++) {
        if (kt + 1 < E_DIM / KSTAGE) {
            load_stage(buf ^ 1, kt + 1);
            CP_COMMIT();
            CP_WAIT(1);
        } else {
            CP_WAIT(0);
        }
        __syncthreads();

        uint32_t stA = sbase + buf * STAGE_B;
        uint32_t stW = stA + 2 * TILE_B;
#pragma unroll
        for (int k16 = 0; k16 < 2; k16++) {
            uint32_t aH[2][4], aL[2][4], bW[4][4];
#pragma unroll
            for (int mt = 0; mt < 2; mt++) {
                uint32_t ad = stA + a_off + mt * (16 * ROWB) + k16 * 32;
                ldm_x4(aH[mt][0], aH[mt][1], aH[mt][2], aH[mt][3], ad);
                ldm_x4(aL[mt][0], aL[mt][1], aL[mt][2], aL[mt][3], ad + TILE_B);
            }
#pragma unroll
            for (int p = 0; p < 4; p++) {
                uint32_t bd = stW + b_off + p * (16 * ROWB) + k16 * 32;
                ldm_x4(bW[p][0], bW[p][1], bW[p][2], bW[p][3], bd);
            }
#pragma unroll
            for (int mt = 0; mt < 2; mt++)
#pragma unroll
                for (int nt = 0; nt < 8; nt++)
                    mma_f16(acc[mt][nt], aH[mt], bW[nt >> 1][(nt & 1) * 2],
                            bW[nt >> 1][(nt & 1) * 2 + 1]);
#pragma unroll
            for (int mt = 0; mt < 2; mt++)
#pragma unroll
                for (int nt = 0; nt < 8; nt++)
                    mma_f16(acc[mt][nt], aL[mt], bW[nt >> 1][(nt & 1) * 2],
                            bW[nt >> 1][(nt & 1) * 2 + 1]);
        }
        __syncthreads();
        buf ^= 1;
    }

#pragma unroll
    for (int mt = 0; mt < 2; mt++) {
        int row_base = m0 + warp_m * 32 + mt * 16 + (lane >> 2);
#pragma unroll
        for (int half = 0; half < 2; half++) {
            int m = row_base + half * 8;
            int bidx = m / S;
            int sidx = m - bidx * S;
#pragma unroll
            for (int nt = 0; nt < 8; nt++) {
                int col = n0 + warp_n * 64 + nt * 8 + (lane & 3) * 2;
                float vx = acc[mt][nt][half * 2 + 0] + bias[col + 0];
                float vy = acc[mt][nt][half * 2 + 1] + bias[col + 1];
                if (MODE == 2) {
                    float2 v; v.x = vx; v.y = vy;
                    *((float2*)(C + (size_t)m * E_DIM + col)) = v;
                } else {
                    int hh = col >> 6;
                    int dd = col & 63;
                    size_t off = (((size_t)(bidx * N_HEADS + hh)) * S + sidx) * D_HEAD + dd;
                    __half2 hp = __floats2half2_rn(vx, vy);
                    *(__half2*)(Ch + off) = hp;
                    if (MODE == 0) {
                        float2 hf = __half22float2(hp);
                        __half2 lp = __floats2half2_rn(vx - hf.x, vy - hf.y);
                        *(__half2*)(Cl + off) = lp;
                    }
                }
            }
        }
    }
}

// ---------------- HMMA flash attention, fp16, 2-pass ----------------
// Q hi/lo fp16 (register-resident), K/V single fp16, P split in-kernel.
#define AROW    144                 // bytes per 64-elem fp16 row (+16 pad)
#define Q_BYTES (128 * AROW)        // 18432 per half
#define KV_TILE (64 * AROW)         // 9216
#define KV_STG  (2 * KV_TILE)       // K, V = 18432
#define AT_Q    0
#define AT_KV   (2 * Q_BYTES)       // 36864
#define AT_MS   (AT_KV + 2 * KV_STG)  // 73728
#define AT_SMEM (AT_MS + K_LEN * 4)   // 81920

__global__ __launch_bounds__(256, 1)
void attention_tc_kernel(const __half* __restrict__ qh_g,
                         const __half* __restrict__ ql_g,
                         const __half* __restrict__ k_g,
                         const __half* __restrict__ v_g,
                         __half* __restrict__ oh_g,
                         __half* __restrict__ ol_g) {
    extern __shared__ char sm[];
    uint32_t sbase = smem_u32(sm);
    int tid = threadIdx.x;
    int lane = tid & 31;
    int wid = tid >> 5;
    int qt = blockIdx.x;
    int h = blockIdx.y;
    int b = blockIdx.z;
    int bh = b * N_HEADS + h;

    // Q (hi/lo) + mask loads
    {
        const __half* qs[2] = {qh_g, ql_g};
#pragma unroll
        for (int i = 0; i < 8; i++) {
            int c = tid + i * 256;
            int half = c >> 10, rem = c & 1023;
            int row = rem >> 3, seg = rem & 7;
            uint32_t dst = sbase + AT_Q + half * Q_BYTES + row * AROW + seg * 16;
            CP_ASYNC16(dst, qs[half] + ((size_t)(bh * Q_LEN + qt * 128 + row)) * 64 + seg * 8);
        }
        const float* msrc = g_maskf + b * K_LEN;
#pragma unroll
        for (int i = 0; i < 2; i++) {
            int c = tid + i * 256;
            CP_ASYNC16(sbase + AT_MS + c * 16, msrc + c * 4);
        }
    }
    CP_COMMIT();

    const __half* kvs[2] = {k_g, v_g};
    auto load_kv = [&](int buf, int kt) {
        uint32_t SB = sbase + AT_KV + buf * KV_STG;
#pragma unroll
        for (int i = 0; i < 4; i++) {
            int c = tid + i * 256;
            int t = c >> 9, rem = c & 511;
            int row = rem >> 3, seg = rem & 7;
            CP_ASYNC16(SB + t * KV_TILE + row * AROW + seg * 16,
                       kvs[t] + ((size_t)(bh * K_LEN + kt * 64 + row)) * 64 + seg * 8);
        }
    };
    load_kv(0, 0);
    CP_COMMIT();
    CP_WAIT(1);            // Q + mask complete
    __syncthreads();

    // Q fragments (register resident for whole kernel)
    uint32_t qfh[4][4], qfl[4][4];
    {
        uint32_t qaddr = sbase + AT_Q + (wid * 16 + (lane & 15)) * AROW + (lane >> 4) * 16;
#pragma unroll
        for (int c2 = 0; c2 < 4; c2++) {
            ldm_x4(qfh[c2][0], qfh[c2][1], qfh[c2][2], qfh[c2][3], qaddr + c2 * 32);
            ldm_x4(qfl[c2][0], qfl[c2][1], qfl[c2][2], qfl[c2][3], qaddr + Q_BYTES + c2 * 32);
        }
    }

    float oacc[8][4];
#pragma unroll
    for (int i = 0; i < 8; i++)
#pragma unroll
        for (int j = 0; j < 4; j++) oacc[i][j] = 0.0f;
    float m0 = -50000.0f, m1 = -50000.0f, l0 = 0.0f, l1 = 0.0f;

    for (int kt = 0; kt < K_LEN / 64; kt++) {
        int buf = kt & 1;
        if (kt + 1 < K_LEN / 64) {
            load_kv(buf ^ 1, kt + 1);
            CP_COMMIT();
            CP_WAIT(1);
        } else {
            CP_WAIT(0);
        }
        __syncthreads();

        uint32_t SB = sbase + AT_KV + buf * KV_STG;

        // S = Q K^T (2-pass: Qh, Ql), fp32 accum
        float sacc[8][4];
#pragma unroll
        for (int i = 0; i < 8; i++)
#pragma unroll
            for (int j = 0; j < 4; j++) sacc[i][j] = 0.0f;
#pragma unroll
        for (int c2 = 0; c2 < 4; c2++) {
            uint32_t kf[4][4];
#pragma unroll
            for (int p = 0; p < 4; p++) {
                uint32_t kaddr = SB + (uint32_t)((p * 16 + (lane >> 4) * 8 + (lane & 7)) * AROW
                               + ((lane >> 3) & 1) * 16 + c2 * 32);
                ldm_x4(kf[p][0], kf[p][1], kf[p][2], kf[p][3], kaddr);
            }
#pragma unroll
            for (int nt = 0; nt < 8; nt++) {
                uint32_t b0 = kf[nt >> 1][(nt & 1) * 2], b1 = kf[nt >> 1][(nt & 1) * 2 + 1];
                mma_f16(sacc[nt], qfh[c2], b0, b1);
                mma_f16(sacc[nt], qfl[c2], b0, b1);
            }
        }

        // scale to log2 domain + mask
        const float* msp = (const float*)(sm + AT_MS) + kt * 64;
#pragma unroll
        for (int nt = 0; nt < 8; nt++) {
            float2 mv = *(const float2*)(msp + nt * 8 + (lane & 3) * 2);
            sacc[nt][0] = fmaf(sacc[nt][0], SC_LOG2, mv.x);
            sacc[nt][1] = fmaf(sacc[nt][1], SC_LOG2, mv.y);
            sacc[nt][2] = fmaf(sacc[nt][2], SC_LOG2, mv.x);
            sacc[nt][3] = fmaf(sacc[nt][3], SC_LOG2, mv.y);
        }

        // online softmax (rows r0 = lane>>2, r1 = r0+8)
        float mx0 = sacc[0][0], mx1 = sacc[0][2];
#pragma unroll
        for (int nt = 0; nt < 8; nt++) {
            mx0 = fmaxf(mx0, fmaxf(sacc[nt][0], sacc[nt][1]));
            mx1 = fmaxf(mx1, fmaxf(sacc[nt][2], sacc[nt][3]));
        }
        mx0 = fmaxf(mx0, __shfl_xor_sync(0xffffffffu, mx0, 1));
        mx0 = fmaxf(mx0, __shfl_xor_sync(0xffffffffu, mx0, 2));
        mx1 = fmaxf(mx1, __shfl_xor_sync(0xffffffffu, mx1, 1));
        mx1 = fmaxf(mx1, __shfl_xor_sync(0xffffffffu, mx1, 2));
        float nm0 = fmaxf(m0, mx0), nm1 = fmaxf(m1, mx1);
        float a0 = ex2f(m0 - nm0), a1 = ex2f(m1 - nm1);
        m0 = nm0; m1 = nm1;

        float s0 = 0.0f, s1 = 0.0f;
#pragma unroll
        for (int nt = 0; nt < 8; nt++) {
            sacc[nt][0] = ex2f(sacc[nt][0] - nm0);
            sacc[nt][1] = ex2f(sacc[nt][1] - nm0);
            sacc[nt][2] = ex2f(sacc[nt][2] - nm1);
            sacc[nt][3] = ex2f(sacc[nt][3] - nm1);
            s0 += sacc[nt][0] + sacc[nt][1];
            s1 += sacc[nt][2] + sacc[nt][3];
        }
        s0 += __shfl_xor_sync(0xffffffffu, s0, 1);
        s0 += __shfl_xor_sync(0xffffffffu, s0, 2);
        s1 += __shfl_xor_sync(0xffffffffu, s1, 1);
        s1 += __shfl_xor_sync(0xffffffffu, s1, 2);
        l0 = l0 * a0 + s0;
        l1 = l1 * a1 + s1;
#pragma unroll
        for (int nf = 0; nf < 8; nf++) {
            oacc[nf][0] *= a0; oacc[nf][1] *= a0;
            oacc[nf][2] *= a1; oacc[nf][3] *= a1;
        }

        // O += P V (2-pass: Ph, Pl)
#pragma unroll
        for (int j = 0; j < 4; j++) {
            uint32_t ph[4], pl[4];
#pragma unroll
            for (int half = 0; half < 2; half++) {
                int f = 2 * j + half;
                // a0 = (r0, k 0-7), a1 = (r1, k 0-7), a2 = (r0, k 8-15), a3 = (r1, k 8-15)
                __half2 h01 = __floats2half2_rn(sacc[f][0], sacc[f][1]);
                __half2 h23 = __floats2half2_rn(sacc[f][2], sacc[f][3]);
                float2 f01 = __half22float2(h01);
                float2 f23 = __half22float2(h23);
                __half2 l01 = __floats2half2_rn(sacc[f][0] - f01.x, sacc[f][1] - f01.y);
                __half2 l23 = __floats2half2_rn(sacc[f][2] - f23.x, sacc[f][3] - f23.y);
                ph[half ? 2 : 0] = *(uint32_t*)&h01;
                ph[half ? 3 : 1] = *(uint32_t*)&h23;
                pl[half ? 2 : 0] = *(uint32_t*)&l01;
                pl[half ? 3 : 1] = *(uint32_t*)&l23;
            }
#pragma unroll
            for (int q2b = 0; q2b < 4; q2b++) {
                uint32_t vf[4];
                uint32_t vaddr = SB + KV_TILE
                               + (uint32_t)((j * 16 + (lane & 15)) * AROW
                               + q2b * 32 + (lane >> 4) * 16);
                ldm_x4t(vf[0], vf[1], vf[2], vf[3], vaddr);
                mma_f16(oacc[q2b * 2 + 0], ph, vf[0], vf[1]);
                mma_f16(oacc[q2b * 2 + 0], pl, vf[0], vf[1]);
                mma_f16(oacc[q2b * 2 + 1], ph, vf[2], vf[3]);
                mma_f16(oacc[q2b * 2 + 1], pl, vf[2], vf[3]);
            }
        }
        __syncthreads();
    }

    // epilogue: normalize, split to fp16 hi/lo, write [B*Q, E]
    float inv0 = 1.0f / l0, inv1 = 1.0f / l1;
    int qrow = qt * 128 + wid * 16 + (lane >> 2);
    size_t row0 = (size_t)b * Q_LEN + qrow;
    size_t row1 = row0 + 8;
#pragma unroll
    for (int nf = 0; nf < 8; nf++) {
        int col = h * 64 + nf * 8 + (lane & 3) * 2;
        {
            float vx = oacc[nf][0] * inv0, vy = oacc[nf][1] * inv0;
            __half2 hp = __floats2half2_rn(vx, vy);
            float2 hf = __half22float2(hp);
            __half2 lp = __floats2half2_rn(vx - hf.x, vy - hf.y);
            *(__half2*)(oh_g + row0 * E_DIM + col) = hp;
            *(__half2*)(ol_g + row0 * E_DIM + col) = lp;
        }
        {
            float vx = oacc[nf][2] * inv1, vy = oacc[nf][3] * inv1;
            __half2 hp = __floats2half2_rn(vx, vy);
            float2 hf = __half22float2(hp);
            __half2 lp = __floats2half2_rn(vx - hf.x, vy - hf.y);
            *(__half2*)(oh_g + row1 * E_DIM + col) = hp;
            *(__half2*)(ol_g + row1 * E_DIM + col) = lp;
        }
    }
}

// ---------------- launch ----------------
extern "C" void kernel_launch(void* const* d_in, const int* in_sizes, int n_in,
                              void* d_out, int out_size) {
    const float* query = (const float*)d_in[0];
    const float* key   = (const float*)d_in[1];
    const float* value = (const float*)d_in[2];
    const unsigned char* mask = (const unsigned char*)d_in[3];
    const float* Wq = (const float*)d_in[4];
    const float* bq = (const float*)d_in[5];
    const float* Wk = (const float*)d_in[6];
    const float* bk = (const float*)d_in[7];
    const float* Wv = (const float*)d_in[8];
    const float* bv = (const float*)d_in[9];
    const float* Wo = (const float*)d_in[10];
    const float* bo = (const float*)d_in[11];
    float* out = (float*)d_out;

    __half *qh, *ql, *kh, *kl, *vh, *vl, *aoh, *aol;
    __half *wq16, *wk16, *wv16, *wo16;
    __half *pqh, *pql, *pk16, *pv16;
    cudaGetSymbolAddress((void**)&qh, g_qh);     cudaGetSymbolAddress((void**)&ql, g_ql);
    cudaGetSymbolAddress((void**)&kh, g_kh);     cudaGetSymbolAddress((void**)&kl, g_kl);
    cudaGetSymbolAddress((void**)&vh, g_vh);     cudaGetSymbolAddress((void**)&vl, g_vl);
    cudaGetSymbolAddress((void**)&aoh, g_aoh);   cudaGetSymbolAddress((void**)&aol, g_aol);
    cudaGetSymbolAddress((void**)&wq16, g_wq16); cudaGetSymbolAddress((void**)&wk16, g_wk16);
    cudaGetSymbolAddress((void**)&wv16, g_wv16); cudaGetSymbolAddress((void**)&wo16, g_wo16);
    cudaGetSymbolAddress((void**)&pqh, g_pqh);   cudaGetSymbolAddress((void**)&pql, g_pql);
    cudaGetSymbolAddress((void**)&pk16, g_pk16); cudaGetSymbolAddress((void**)&pv16, g_pv16);

    mask_prep_kernel<<<1, 256>>>(mask);

    split16_kernel<<<512, 256>>>(query, qh, ql, (B_SZ * Q_LEN * E_DIM) / 4);
    split16_kernel<<<512, 256>>>(key,   kh, kl, (B_SZ * K_LEN * E_DIM) / 4);
    split16_kernel<<<512, 256>>>(value, vh, vl, (B_SZ * K_LEN * E_DIM) / 4);
    conv16_kernel<<<dim3(128, 4), 256>>>(Wq, Wk, Wv, Wo, wq16, wk16, wv16, wo16,
                                         (E_DIM * E_DIM) / 4);

    cudaFuncSetAttribute(gemm_tc_kernel<0>, cudaFuncAttributeMaxDynamicSharedMemorySize, GEMM_SMEM);
    cudaFuncSetAttribute(gemm_tc_kernel<1>, cudaFuncAttributeMaxDynamicSharedMemorySize, GEMM_SMEM);
    cudaFuncSetAttribute(gemm_tc_kernel<2>, cudaFuncAttributeMaxDynamicSharedMemorySize, GEMM_SMEM);

    gemm_tc_kernel<0><<<dim3(8, 16), 256, GEMM_SMEM>>>(qh, ql, wq16, bq,
                                                       nullptr, pqh, pql, B_SZ * Q_LEN, Q_LEN);
    gemm_tc_kernel<1><<<dim3(8, 32), 256, GEMM_SMEM>>>(kh, kl, wk16, bk,
                                                       nullptr, pk16, nullptr, B_SZ * K_LEN, K_LEN);
    gemm_tc_kernel<1><<<dim3(8, 32), 256, GEMM_SMEM>>>(vh, vl, wv16, bv,
                                                       nullptr, pv16, nullptr, B_SZ * K_LEN, K_LEN);

    cudaFuncSetAttribute(attention_tc_kernel, cudaFuncAttributeMaxDynamicSharedMemorySize, AT_SMEM);
    attention_tc_kernel<<<dim3(Q_LEN / 128, N_HEADS, B_SZ), 256, AT_SMEM>>>(
        pqh, pql, pk16, pv16, aoh, aol);

    gemm_tc_kernel<2><<<dim3(8, 16), 256, GEMM_SMEM>>>(aoh, aol, wo16, bo,
                                                       out, nullptr, nullptr, B_SZ * Q_LEN, Q_LEN);
}

// round 7
// speedup vs baseline: 5.9364x; 1.4398x over previous
#include <cuda_runtime.h>
#include <cuda_fp16.h>
#include <cstdint>

#define B_SZ    2
#define Q_LEN   1024
#define K_LEN   2048
#define E_DIM   1024
#define N_HEADS 16
#define D_HEAD  64
// 0.125 * log2(e)
#define SC_LOG2 0.1803368801111204f

// ---------------- scratch (static device globals; no allocation) ----------------
__device__ __align__(16) float g_maskf[B_SZ * K_LEN];                  // 0 or -1e30

// fp16 converts of inputs (GEMM A operands)
__device__ __align__(16) __half g_q16[B_SZ * Q_LEN * E_DIM];
__device__ __align__(16) __half g_k16[B_SZ * K_LEN * E_DIM];
__device__ __align__(16) __half g_v16[B_SZ * K_LEN * E_DIM];
// weights fp16
__device__ __align__(16) __half g_wq16[E_DIM * E_DIM];
__device__ __align__(16) __half g_wk16[E_DIM * E_DIM];
__device__ __align__(16) __half g_wv16[E_DIM * E_DIM];
__device__ __align__(16) __half g_wo16[E_DIM * E_DIM];
// projected q/k/v fp16 in [B,H,S,D]
__device__ __align__(16) __half g_pq16[B_SZ * N_HEADS * Q_LEN * D_HEAD];
__device__ __align__(16) __half g_pk16[B_SZ * N_HEADS * K_LEN * D_HEAD];
__device__ __align__(16) __half g_pv16[B_SZ * N_HEADS * K_LEN * D_HEAD];
// attention output fp16 in [B*Q, E]
__device__ __align__(16) __half g_ao16[B_SZ * Q_LEN * E_DIM];

// ---------------- PTX helpers (portable sm_80+ only) ----------------
__device__ __forceinline__ uint32_t smem_u32(const void* p) {
    uint32_t a;
    asm("{ .reg .u64 t; cvta.to.shared.u64 t, %1; cvt.u32.u64 %0, t; }" : "=r"(a) : "l"(p));
    return a;
}
#define CP_ASYNC16(dst, src) \
    asm volatile("cp.async.cg.shared.global [%0], [%1], 16;" :: "r"(dst), "l"(src))
#define CP_COMMIT() asm volatile("cp.async.commit_group;" ::: "memory")
#define CP_WAIT(N)  asm volatile("cp.async.wait_group %0;" :: "n"(N) : "memory")

__device__ __forceinline__ void ldm_x4(uint32_t& r0, uint32_t& r1, uint32_t& r2,
                                       uint32_t& r3, uint32_t addr) {
    asm volatile("ldmatrix.sync.aligned.m8n8.x4.shared.b16 {%0,%1,%2,%3}, [%4];"
                 : "=r"(r0), "=r"(r1), "=r"(r2), "=r"(r3) : "r"(addr));
}
__device__ __forceinline__ void ldm_x4t(uint32_t& r0, uint32_t& r1, uint32_t& r2,
                                        uint32_t& r3, uint32_t addr) {
    asm volatile("ldmatrix.sync.aligned.m8n8.x4.trans.shared.b16 {%0,%1,%2,%3}, [%4];"
                 : "=r"(r0), "=r"(r1), "=r"(r2), "=r"(r3) : "r"(addr));
}
__device__ __forceinline__ void mma_f16(float* c, const uint32_t* a,
                                        uint32_t b0, uint32_t b1) {
    asm volatile(
        "mma.sync.aligned.m16n8k16.row.col.f32.f16.f16.f32 "
        "{%0,%1,%2,%3}, {%4,%5,%6,%7}, {%8,%9}, {%0,%1,%2,%3};"
        : "+f"(c[0]), "+f"(c[1]), "+f"(c[2]), "+f"(c[3])
        : "r"(a[0]), "r"(a[1]), "r"(a[2]), "r"(a[3]), "r"(b0), "r"(b1));
}
__device__ __forceinline__ float ex2f(float x) {
    float y; asm("ex2.approx.ftz.f32 %0, %1;" : "=f"(y) : "f"(x)); return y;
}

// ---------------- mask prep (dtype sniffing) ----------------
__global__ void mask_prep_kernel(const unsigned char* __restrict__ raw) {
    const int NM = B_SZ * K_LEN;
    int tid = threadIdx.x;
    int gt1 = 0, off = 0, low = 0;
    for (int i = tid; i < NM; i += 256) {
        unsigned char c = raw[i];
        if (c > 1) gt1 = 1;
        if ((i & 3) != 0 && c != 0) off = 1;
        if ((i & 3) == 0 && c != 0) low = 1;
    }
    int any_gt1 = __syncthreads_or(gt1);
    int any_off = __syncthreads_or(off);
    int any_low = __syncthreads_or(low);
    for (int i = tid; i < NM; i += 256) {
        bool mval;
        if (any_gt1) {
            if (any_low) mval = (((const unsigned short*)raw)[i] != 0);
            else         mval = (((const float*)raw)[i] != 0.0f);
        } else {
            if (any_off) mval = (raw[i] != 0);
            else         mval = (((const int*)raw)[i] != 0);
        }
        g_maskf[i] = mval ? -1e30f : 0.0f;
    }
}

// ---------------- fp32 -> fp16 convert ----------------
__global__ __launch_bounds__(256)
void convA_kernel(const float* __restrict__ x, __half* __restrict__ o, int n4) {
    int i = blockIdx.x * 256 + threadIdx.x;
    int stride = gridDim.x * 256;
    for (; i < n4; i += stride) {
        float4 v = ((const float4*)x)[i];
        ((__half2*)o)[i * 2 + 0] = __floats2half2_rn(v.x, v.y);
        ((__half2*)o)[i * 2 + 1] = __floats2half2_rn(v.z, v.w);
    }
}
__global__ __launch_bounds__(256)
void conv16_kernel(const float* __restrict__ w0, const float* __restrict__ w1,
                   const float* __restrict__ w2, const float* __restrict__ w3,
                   __half* __restrict__ o0, __half* __restrict__ o1,
                   __half* __restrict__ o2, __half* __restrict__ o3, int n4) {
    const float* srcs[4] = {w0, w1, w2, w3};
    __half* dsts[4] = {o0, o1, o2, o3};
    const float* x = srcs[blockIdx.y];
    __half* o = dsts[blockIdx.y];
    int i = blockIdx.x * 256 + threadIdx.x;
    int stride = gridDim.x * 256;
    for (; i < n4; i += stride) {
        float4 v = ((const float4*)x)[i];
        ((__half2*)o)[i * 2 + 0] = __floats2half2_rn(v.x, v.y);
        ((__half2*)o)[i * 2 + 1] = __floats2half2_rn(v.z, v.w);
    }
}

// ---------------- HMMA fp16 GEMM: C = A @ W^T + bias ----------------
// MODE 0: fp16 out scattered [B,H,S,D]; MODE 2: fp32 [M,N].
#define KSTAGE     32
#define ROWB       80
#define TILE_B     (128 * ROWB)
#define STAGE_B    (2 * TILE_B)          // A, W
#define GEMM_SMEM  (2 * STAGE_B)         // 40960

template <int MODE>
__global__ __launch_bounds__(256)
void gemm_tc_kernel(const __half* __restrict__ A16,
                    const __half* __restrict__ W16,
                    const float* __restrict__ bias,
                    float* __restrict__ C,
                    __half* __restrict__ Ch,
                    int M, int S) {
    extern __shared__ char sm[];
    uint32_t sbase = smem_u32(sm);

    int tid = threadIdx.x;
    int wid = tid >> 5;
    int lane = tid & 31;
    int m0 = blockIdx.y * 128;
    int n0 = blockIdx.x * 128;
    int warp_m = wid & 3;
    int warp_n = wid >> 2;

    const __half* srcs[2] = {A16, W16};

    auto load_stage = [&](int buf, int kt) {
        uint32_t dst_base = sbase + buf * STAGE_B;
#pragma unroll
        for (int t = 0; t < 2; t++) {
            const __half* src = srcs[t] + (size_t)(t == 0 ? m0 : n0) * E_DIM + kt * KSTAGE;
#pragma unroll
            for (int j = 0; j < 2; j++) {
                int s = tid + j * 256;
                int row = s >> 2;
                int c16 = s & 3;
                uint32_t dst = dst_base + t * TILE_B + row * ROWB + c16 * 16;
                CP_ASYNC16(dst, (const char*)(src + (size_t)row * E_DIM + c16 * 8));
            }
        }
    };

    uint32_t a_off = (uint32_t)((warp_m * 32 + (lane & 15)) * ROWB + (lane >> 4) * 16);
    uint32_t b_off = (uint32_t)((warp_n * 64 + ((lane >> 4) * 8) + (lane & 7)) * ROWB
                                + ((lane >> 3) & 1) * 16);

    float acc[2][8][4];
#pragma unroll
    for (int i = 0; i < 2; i++)
#pragma unroll
        for (int j = 0; j < 8; j++)
#pragma unroll
            for (int k = 0; k < 4; k++) acc[i][j][k] = 0.0f;

    load_stage(0, 0);
    CP_COMMIT();

    int buf = 0;
    for (int kt = 0; kt < E_DIM / KSTAGE; kt++) {
        if (kt + 1 < E_DIM / KSTAGE) {
            load_stage(buf ^ 1, kt + 1);
            CP_COMMIT();
            CP_WAIT(1);
        } else {
            CP_WAIT(0);
        }
        __syncthreads();

        uint32_t stA = sbase + buf * STAGE_B;
        uint32_t stW = stA + TILE_B;
#pragma unroll
        for (int k16 = 0; k16 < 2; k16++) {
            uint32_t aA[2][4], bW[4][4];
#pragma unroll
            for (int mt = 0; mt < 2; mt++) {
                uint32_t ad = stA + a_off + mt * (16 * ROWB) + k16 * 32;
                ldm_x4(aA[mt][0], aA[mt][1], aA[mt][2], aA[mt][3], ad);
            }
#pragma unroll
            for (int p = 0; p < 4; p++) {
                uint32_t bd = stW + b_off + p * (16 * ROWB) + k16 * 32;
                ldm_x4(bW[p][0], bW[p][1], bW[p][2], bW[p][3], bd);
            }
#pragma unroll
            for (int mt = 0; mt < 2; mt++)
#pragma unroll
                for (int nt = 0; nt < 8; nt++)
                    mma_f16(acc[mt][nt], aA[mt], bW[nt >> 1][(nt & 1) * 2],
                            bW[nt >> 1][(nt & 1) * 2 + 1]);
        }
        __syncthreads();
        buf ^= 1;
    }

#pragma unroll
    for (int mt = 0; mt < 2; mt++) {
        int row_base = m0 + warp_m * 32 + mt * 16 + (lane >> 2);
#pragma unroll
        for (int half = 0; half < 2; half++) {
            int m = row_base + half * 8;
            int bidx = m / S;
            int sidx = m - bidx * S;
#pragma unroll
            for (int nt = 0; nt < 8; nt++) {
                int col = n0 + warp_n * 64 + nt * 8 + (lane & 3) * 2;
                float vx = acc[mt][nt][half * 2 + 0] + bias[col + 0];
                float vy = acc[mt][nt][half * 2 + 1] + bias[col + 1];
                if (MODE == 2) {
                    float2 v; v.x = vx; v.y = vy;
                    *((float2*)(C + (size_t)m * E_DIM + col)) = v;
                } else {
                    int hh = col >> 6;
                    int dd = col & 63;
                    size_t off = (((size_t)(bidx * N_HEADS + hh)) * S + sidx) * D_HEAD + dd;
                    *(__half2*)(Ch + off) = __floats2half2_rn(vx, vy);
                }
            }
        }
    }
}

// ---------------- HMMA flash attention, fp16 single-pass ----------------
#define AROW    144                   // bytes per 64-elem fp16 row (+16 pad)
#define Q_BYTES (128 * AROW)          // 18432
#define KV_TILE (64 * AROW)           // 9216
#define KV_STG  (2 * KV_TILE)         // K, V = 18432
#define AT_Q    0
#define AT_KV   Q_BYTES               // 18432
#define AT_MS   (AT_KV + 2 * KV_STG)  // 55296
#define AT_SMEM (AT_MS + K_LEN * 4)   // 63488

__global__ __launch_bounds__(256, 1)
void attention_tc_kernel(const __half* __restrict__ q_g,
                         const __half* __restrict__ k_g,
                         const __half* __restrict__ v_g,
                         __half* __restrict__ o_g) {
    extern __shared__ char sm[];
    uint32_t sbase = smem_u32(sm);
    int tid = threadIdx.x;
    int lane = tid & 31;
    int wid = tid >> 5;
    int qt = blockIdx.x;
    int h = blockIdx.y;
    int b = blockIdx.z;
    int bh = b * N_HEADS + h;

    // Q + mask loads
    {
#pragma unroll
        for (int i = 0; i < 4; i++) {
            int c = tid + i * 256;
            int row = c >> 3, seg = c & 7;
            uint32_t dst = sbase + AT_Q + row * AROW + seg * 16;
            CP_ASYNC16(dst, q_g + ((size_t)(bh * Q_LEN + qt * 128 + row)) * 64 + seg * 8);
        }
        const float* msrc = g_maskf + b * K_LEN;
#pragma unroll
        for (int i = 0; i < 2; i++) {
            int c = tid + i * 256;
            CP_ASYNC16(sbase + AT_MS + c * 16, msrc + c * 4);
        }
    }
    CP_COMMIT();

    const __half* kvs[2] = {k_g, v_g};
    auto load_kv = [&](int buf, int kt) {
        uint32_t SB = sbase + AT_KV + buf * KV_STG;
#pragma unroll
        for (int i = 0; i < 4; i++) {
            int c = tid + i * 256;
            int t = c >> 9, rem = c & 511;
            int row = rem >> 3, seg = rem & 7;
            CP_ASYNC16(SB + t * KV_TILE + row * AROW + seg * 16,
                       kvs[t] + ((size_t)(bh * K_LEN + kt * 64 + row)) * 64 + seg * 8);
        }
    };
    load_kv(0, 0);
    CP_COMMIT();
    CP_WAIT(1);            // Q + mask complete
    __syncthreads();

    // Q fragments (register resident for whole kernel)
    uint32_t qf[4][4];
    {
        uint32_t qaddr = sbase + AT_Q + (wid * 16 + (lane & 15)) * AROW + (lane >> 4) * 16;
#pragma unroll
        for (int c2 = 0; c2 < 4; c2++)
            ldm_x4(qf[c2][0], qf[c2][1], qf[c2][2], qf[c2][3], qaddr + c2 * 32);
    }

    float oacc[8][4];
#pragma unroll
    for (int i = 0; i < 8; i++)
#pragma unroll
        for (int j = 0; j < 4; j++) oacc[i][j] = 0.0f;
    float m0 = -50000.0f, m1 = -50000.0f, l0 = 0.0f, l1 = 0.0f;

    for (int kt = 0; kt < K_LEN / 64; kt++) {
        int buf = kt & 1;
        if (kt + 1 < K_LEN / 64) {
            load_kv(buf ^ 1, kt + 1);
            CP_COMMIT();
            CP_WAIT(1);
        } else {
            CP_WAIT(0);
        }
        __syncthreads();

        uint32_t SB = sbase + AT_KV + buf * KV_STG;

        // S = Q K^T, fp32 accum
        float sacc[8][4];
#pragma unroll
        for (int i = 0; i < 8; i++)
#pragma unroll
            for (int j = 0; j < 4; j++) sacc[i][j] = 0.0f;
#pragma unroll
        for (int c2 = 0; c2 < 4; c2++) {
            uint32_t kf[4][4];
#pragma unroll
            for (int p = 0; p < 4; p++) {
                uint32_t kaddr = SB + (uint32_t)((p * 16 + (lane >> 4) * 8 + (lane & 7)) * AROW
                               + ((lane >> 3) & 1) * 16 + c2 * 32);
                ldm_x4(kf[p][0], kf[p][1], kf[p][2], kf[p][3], kaddr);
            }
#pragma unroll
            for (int nt = 0; nt < 8; nt++)
                mma_f16(sacc[nt], qf[c2], kf[nt >> 1][(nt & 1) * 2],
                        kf[nt >> 1][(nt & 1) * 2 + 1]);
        }

        // scale to log2 domain + mask
        const float* msp = (const float*)(sm + AT_MS) + kt * 64;
#pragma unroll
        for (int nt = 0; nt < 8; nt++) {
            float2 mv = *(const float2*)(msp + nt * 8 + (lane & 3) * 2);
            sacc[nt][0] = fmaf(sacc[nt][0], SC_LOG2, mv.x);
            sacc[nt][1] = fmaf(sacc[nt][1], SC_LOG2, mv.y);
            sacc[nt][2] = fmaf(sacc[nt][2], SC_LOG2, mv.x);
            sacc[nt][3] = fmaf(sacc[nt][3], SC_LOG2, mv.y);
        }

        // online softmax (rows r0 = lane>>2, r1 = r0+8)
        float mx0 = sacc[0][0], mx1 = sacc[0][2];
#pragma unroll
        for (int nt = 0; nt < 8; nt++) {
            mx0 = fmaxf(mx0, fmaxf(sacc[nt][0], sacc[nt][1]));
            mx1 = fmaxf(mx1, fmaxf(sacc[nt][2], sacc[nt][3]));
        }
        mx0 = fmaxf(mx0, __shfl_xor_sync(0xffffffffu, mx0, 1));
        mx0 = fmaxf(mx0, __shfl_xor_sync(0xffffffffu, mx0, 2));
        mx1 = fmaxf(mx1, __shfl_xor_sync(0xffffffffu, mx1, 1));
        mx1 = fmaxf(mx1, __shfl_xor_sync(0xffffffffu, mx1, 2));
        float nm0 = fmaxf(m0, mx0), nm1 = fmaxf(m1, mx1);
        float a0 = ex2f(m0 - nm0), a1 = ex2f(m1 - nm1);
        m0 = nm0; m1 = nm1;

        float s0 = 0.0f, s1 = 0.0f;
#pragma unroll
        for (int nt = 0; nt < 8; nt++) {
            sacc[nt][0] = ex2f(sacc[nt][0] - nm0);
            sacc[nt][1] = ex2f(sacc[nt][1] - nm0);
            sacc[nt][2] = ex2f(sacc[nt][2] - nm1);
            sacc[nt][3] = ex2f(sacc[nt][3] - nm1);
            s0 += sacc[nt][0] + sacc[nt][1];
            s1 += sacc[nt][2] + sacc[nt][3];
        }
        s0 += __shfl_xor_sync(0xffffffffu, s0, 1);
        s0 += __shfl_xor_sync(0xffffffffu, s0, 2);
        s1 += __shfl_xor_sync(0xffffffffu, s1, 1);
        s1 += __shfl_xor_sync(0xffffffffu, s1, 2);
        l0 = l0 * a0 + s0;
        l1 = l1 * a1 + s1;
#pragma unroll
        for (int nf = 0; nf < 8; nf++) {
            oacc[nf][0] *= a0; oacc[nf][1] *= a0;
            oacc[nf][2] *= a1; oacc[nf][3] *= a1;
        }

        // O += P V (single pass)
#pragma unroll
        for (int j = 0; j < 4; j++) {
            uint32_t ph[4];
#pragma unroll
            for (int half = 0; half < 2; half++) {
                int f = 2 * j + half;
                // a0 = (r0, k 0-7), a1 = (r1, k 0-7), a2 = (r0, k 8-15), a3 = (r1, k 8-15)
                __half2 h01 = __floats2half2_rn(sacc[f][0], sacc[f][1]);
                __half2 h23 = __floats2half2_rn(sacc[f][2], sacc[f][3]);
                ph[half ? 2 : 0] = *(uint32_t*)&h01;
                ph[half ? 3 : 1] = *(uint32_t*)&h23;
            }
#pragma unroll
            for (int q2b = 0; q2b < 4; q2b++) {
                uint32_t vf[4];
                uint32_t vaddr = SB + KV_TILE
                               + (uint32_t)((j * 16 + (lane & 15)) * AROW
                               + q2b * 32 + (lane >> 4) * 16);
                ldm_x4t(vf[0], vf[1], vf[2], vf[3], vaddr);
                mma_f16(oacc[q2b * 2 + 0], ph, vf[0], vf[1]);
                mma_f16(oacc[q2b * 2 + 1], ph, vf[2], vf[3]);
            }
        }
        __syncthreads();
    }

    // epilogue: normalize, write fp16 [B*Q, E]
    float inv0 = 1.0f / l0, inv1 = 1.0f / l1;
    int qrow = qt * 128 + wid * 16 + (lane >> 2);
    size_t row0 = (size_t)b * Q_LEN + qrow;
    size_t row1 = row0 + 8;
#pragma unroll
    for (int nf = 0; nf < 8; nf++) {
        int col = h * 64 + nf * 8 + (lane & 3) * 2;
        *(__half2*)(o_g + row0 * E_DIM + col) =
            __floats2half2_rn(oacc[nf][0] * inv0, oacc[nf][1] * inv0);
        *(__half2*)(o_g + row1 * E_DIM + col) =
            __floats2half2_rn(oacc[nf][2] * inv1, oacc[nf][3] * inv1);
    }
}

// ---------------- launch ----------------
extern "C" void kernel_launch(void* const* d_in, const int* in_sizes, int n_in,
                              void* d_out, int out_size) {
    const float* query = (const float*)d_in[0];
    const float* key   = (const float*)d_in[1];
    const float* value = (const float*)d_in[2];
    const unsigned char* mask = (const unsigned char*)d_in[3];
    const float* Wq = (const float*)d_in[4];
    const float* bq = (const float*)d_in[5];
    const float* Wk = (const float*)d_in[6];
    const float* bk = (const float*)d_in[7];
    const float* Wv = (const float*)d_in[8];
    const float* bv = (const float*)d_in[9];
    const float* Wo = (const float*)d_in[10];
    const float* bo = (const float*)d_in[11];
    float* out = (float*)d_out;

    __half *q16, *k16, *v16, *ao16;
    __half *wq16, *wk16, *wv16, *wo16;
    __half *pq16, *pk16, *pv16;
    cudaGetSymbolAddress((void**)&q16, g_q16);
    cudaGetSymbolAddress((void**)&k16, g_k16);
    cudaGetSymbolAddress((void**)&v16, g_v16);
    cudaGetSymbolAddress((void**)&ao16, g_ao16);
    cudaGetSymbolAddress((void**)&wq16, g_wq16);
    cudaGetSymbolAddress((void**)&wk16, g_wk16);
    cudaGetSymbolAddress((void**)&wv16, g_wv16);
    cudaGetSymbolAddress((void**)&wo16, g_wo16);
    cudaGetSymbolAddress((void**)&pq16, g_pq16);
    cudaGetSymbolAddress((void**)&pk16, g_pk16);
    cudaGetSymbolAddress((void**)&pv16, g_pv16);

    mask_prep_kernel<<<1, 256>>>(mask);

    convA_kernel<<<512, 256>>>(query, q16, (B_SZ * Q_LEN * E_DIM) / 4);
    convA_kernel<<<512, 256>>>(key,   k16, (B_SZ * K_LEN * E_DIM) / 4);
    convA_kernel<<<512, 256>>>(value, v16, (B_SZ * K_LEN * E_DIM) / 4);
    conv16_kernel<<<dim3(128, 4), 256>>>(Wq, Wk, Wv, Wo, wq16, wk16, wv16, wo16,
                                         (E_DIM * E_DIM) / 4);

    cudaFuncSetAttribute(gemm_tc_kernel<0>, cudaFuncAttributeMaxDynamicSharedMemorySize, GEMM_SMEM);
    cudaFuncSetAttribute(gemm_tc_kernel<2>, cudaFuncAttributeMaxDynamicSharedMemorySize, GEMM_SMEM);

    gemm_tc_kernel<0><<<dim3(8, 16), 256, GEMM_SMEM>>>(q16, wq16, bq,
                                                       nullptr, pq16, B_SZ * Q_LEN, Q_LEN);
    gemm_tc_kernel<0><<<dim3(8, 32), 256, GEMM_SMEM>>>(k16, wk16, bk,
                                                       nullptr, pk16, B_SZ * K_LEN, K_LEN);
    gemm_tc_kernel<0><<<dim3(8, 32), 256, GEMM_SMEM>>>(v16, wv16, bv,
                                                       nullptr, pv16, B_SZ * K_LEN, K_LEN);

    cudaFuncSetAttribute(attention_tc_kernel, cudaFuncAttributeMaxDynamicSharedMemorySize, AT_SMEM);
    attention_tc_kernel<<<dim3(Q_LEN / 128, N_HEADS, B_SZ), 256, AT_SMEM>>>(
        pq16, pk16, pv16, ao16);

    gemm_tc_kernel<2><<<dim3(8, 16), 256, GEMM_SMEM>>>(ao16, wo16, bo,
                                                       out, nullptr, B_SZ * Q_LEN, Q_LEN);
}

// round 8
// speedup vs baseline: 6.5752x; 1.1076x over previous
#include <cuda_runtime.h>
#include <cuda_fp16.h>
#include <cstdint>

#define B_SZ    2
#define Q_LEN   1024
#define K_LEN   2048
#define E_DIM   1024
#define N_HEADS 16
#define D_HEAD  64
// 0.125 * log2(e)
#define SC_LOG2 0.1803368801111204f

// ---------------- scratch (static device globals; no allocation) ----------------
__device__ __align__(16) float g_maskf[B_SZ * K_LEN];                  // 0 or -1e30

__device__ __align__(16) __half g_q16[B_SZ * Q_LEN * E_DIM];
__device__ __align__(16) __half g_k16[B_SZ * K_LEN * E_DIM];
__device__ __align__(16) __half g_v16[B_SZ * K_LEN * E_DIM];
__device__ __align__(16) __half g_wq16[E_DIM * E_DIM];
__device__ __align__(16) __half g_wk16[E_DIM * E_DIM];
__device__ __align__(16) __half g_wv16[E_DIM * E_DIM];
__device__ __align__(16) __half g_wo16[E_DIM * E_DIM];
__device__ __align__(16) __half g_pq16[B_SZ * N_HEADS * Q_LEN * D_HEAD];
__device__ __align__(16) __half g_pk16[B_SZ * N_HEADS * K_LEN * D_HEAD];
__device__ __align__(16) __half g_pv16[B_SZ * N_HEADS * K_LEN * D_HEAD];
__device__ __align__(16) __half g_ao16[B_SZ * Q_LEN * E_DIM];

// ---------------- PTX helpers (portable sm_80+ only) ----------------
__device__ __forceinline__ uint32_t smem_u32(const void* p) {
    uint32_t a;
    asm("{ .reg .u64 t; cvta.to.shared.u64 t, %1; cvt.u32.u64 %0, t; }" : "=r"(a) : "l"(p));
    return a;
}
#define CP_ASYNC16(dst, src) \
    asm volatile("cp.async.cg.shared.global [%0], [%1], 16;" :: "r"(dst), "l"(src))
#define CP_COMMIT() asm volatile("cp.async.commit_group;" ::: "memory")
#define CP_WAIT(N)  asm volatile("cp.async.wait_group %0;" :: "n"(N) : "memory")

__device__ __forceinline__ void ldm_x4(uint32_t& r0, uint32_t& r1, uint32_t& r2,
                                       uint32_t& r3, uint32_t addr) {
    asm volatile("ldmatrix.sync.aligned.m8n8.x4.shared.b16 {%0,%1,%2,%3}, [%4];"
                 : "=r"(r0), "=r"(r1), "=r"(r2), "=r"(r3) : "r"(addr));
}
__device__ __forceinline__ void ldm_x4t(uint32_t& r0, uint32_t& r1, uint32_t& r2,
                                        uint32_t& r3, uint32_t addr) {
    asm volatile("ldmatrix.sync.aligned.m8n8.x4.trans.shared.b16 {%0,%1,%2,%3}, [%4];"
                 : "=r"(r0), "=r"(r1), "=r"(r2), "=r"(r3) : "r"(addr));
}
__device__ __forceinline__ void mma_f16(float* c, const uint32_t* a,
                                        uint32_t b0, uint32_t b1) {
    asm volatile(
        "mma.sync.aligned.m16n8k16.row.col.f32.f16.f16.f32 "
        "{%0,%1,%2,%3}, {%4,%5,%6,%7}, {%8,%9}, {%0,%1,%2,%3};"
        : "+f"(c[0]), "+f"(c[1]), "+f"(c[2]), "+f"(c[3])
        : "r"(a[0]), "r"(a[1]), "r"(a[2]), "r"(a[3]), "r"(b0), "r"(b1));
}
__device__ __forceinline__ float ex2f(float x) {
    float y; asm("ex2.approx.ftz.f32 %0, %1;" : "=f"(y) : "f"(x)); return y;
}

// ---------------- fused prep: 7 fp32->fp16 converts + mask prep ----------------
// blockIdx.y: 0=query 1=key 2=value 3..6=Wq/Wk/Wv/Wo, 7=mask(block x 0 only)
__global__ __launch_bounds__(256)
void prep_kernel(const float* __restrict__ q, const float* __restrict__ k,
                 const float* __restrict__ v,
                 const float* __restrict__ wq, const float* __restrict__ wk,
                 const float* __restrict__ wv, const float* __restrict__ wo,
                 const unsigned char* __restrict__ mask) {
    int task = blockIdx.y;
    if (task == 7) {
        if (blockIdx.x != 0) return;
        const int NM = B_SZ * K_LEN;
        int tid = threadIdx.x;
        int gt1 = 0, off = 0, low = 0;
        for (int i = tid; i < NM; i += 256) {
            unsigned char c = mask[i];
            if (c > 1) gt1 = 1;
            if ((i & 3) != 0 && c != 0) off = 1;
            if ((i & 3) == 0 && c != 0) low = 1;
        }
        int any_gt1 = __syncthreads_or(gt1);
        int any_off = __syncthreads_or(off);
        int any_low = __syncthreads_or(low);
        for (int i = tid; i < NM; i += 256) {
            bool mval;
            if (any_gt1) {
                if (any_low) mval = (((const unsigned short*)mask)[i] != 0);
                else         mval = (((const float*)mask)[i] != 0.0f);
            } else {
                if (any_off) mval = (mask[i] != 0);
                else         mval = (((const int*)mask)[i] != 0);
            }
            g_maskf[i] = mval ? -1e30f : 0.0f;
        }
        return;
    }
    const float* srcs[7] = {q, k, v, wq, wk, wv, wo};
    __half* dsts[7] = {g_q16, g_k16, g_v16, g_wq16, g_wk16, g_wv16, g_wo16};
    const int n4s[7] = {(B_SZ * Q_LEN * E_DIM) / 4, (B_SZ * K_LEN * E_DIM) / 4,
                        (B_SZ * K_LEN * E_DIM) / 4, (E_DIM * E_DIM) / 4,
                        (E_DIM * E_DIM) / 4, (E_DIM * E_DIM) / 4, (E_DIM * E_DIM) / 4};
    const float* x = srcs[task];
    __half* o = dsts[task];
    int n4 = n4s[task];
    int i = blockIdx.x * 256 + threadIdx.x;
    int stride = gridDim.x * 256;
    for (; i < n4; i += stride) {
        float4 vv = ((const float4*)x)[i];
        ((__half2*)o)[i * 2 + 0] = __floats2half2_rn(vv.x, vv.y);
        ((__half2*)o)[i * 2 + 1] = __floats2half2_rn(vv.z, vv.w);
    }
}

// ---------------- HMMA fp16 GEMM common body ----------------
#define KSTAGE     32
#define ROWB       80
#define TILE_B     (128 * ROWB)
#define STAGE_B    (2 * TILE_B)          // A, W
#define GEMM_SMEM  (2 * STAGE_B)         // 40960

// MODE 0: fp16 out scattered [B,H,S,D]; MODE 2: fp32 [M,N]
template <int MODE>
__device__ __forceinline__
void gemm_body(const __half* __restrict__ A16, const __half* __restrict__ W16,
               const float* __restrict__ bias, float* __restrict__ C,
               __half* __restrict__ Ch, int S, int m0, int n0, char* sm) {
    uint32_t sbase = smem_u32(sm);
    int tid = threadIdx.x;
    int wid = tid >> 5;
    int lane = tid & 31;
    int warp_m = wid & 3;
    int warp_n = wid >> 2;

    auto load_stage = [&](int buf, int kt) {
        uint32_t dst_base = sbase + buf * STAGE_B;
#pragma unroll
        for (int t = 0; t < 2; t++) {
            const __half* src = (t == 0 ? A16 + (size_t)m0 * E_DIM
                                        : W16 + (size_t)n0 * E_DIM) + kt * KSTAGE;
#pragma unroll
            for (int j = 0; j < 2; j++) {
                int s = tid + j * 256;
                int row = s >> 2;
                int c16 = s & 3;
                uint32_t dst = dst_base + t * TILE_B + row * ROWB + c16 * 16;
                CP_ASYNC16(dst, (const char*)(src + (size_t)row * E_DIM + c16 * 8));
            }
        }
    };

    uint32_t a_off = (uint32_t)((warp_m * 32 + (lane & 15)) * ROWB + (lane >> 4) * 16);
    uint32_t b_off = (uint32_t)((warp_n * 64 + ((lane >> 4) * 8) + (lane & 7)) * ROWB
                                + ((lane >> 3) & 1) * 16);

    float acc[2][8][4];
#pragma unroll
    for (int i = 0; i < 2; i++)
#pragma unroll
        for (int j = 0; j < 8; j++)
#pragma unroll
            for (int kk = 0; kk < 4; kk++) acc[i][j][kk] = 0.0f;

    load_stage(0, 0);
    CP_COMMIT();

    int buf = 0;
    for (int kt = 0; kt < E_DIM / KSTAGE; kt++) {
        if (kt + 1 < E_DIM / KSTAGE) {
            load_stage(buf ^ 1, kt + 1);
            CP_COMMIT();
            CP_WAIT(1);
        } else {
            CP_WAIT(0);
        }
        __syncthreads();

        uint32_t stA = sbase + buf * STAGE_B;
        uint32_t stW = stA + TILE_B;
#pragma unroll
        for (int k16 = 0; k16 < 2; k16++) {
            uint32_t aA[2][4], bW[4][4];
#pragma unroll
            for (int mt = 0; mt < 2; mt++) {
                uint32_t ad = stA + a_off + mt * (16 * ROWB) + k16 * 32;
                ldm_x4(aA[mt][0], aA[mt][1], aA[mt][2], aA[mt][3], ad);
            }
#pragma unroll
            for (int p = 0; p < 4; p++) {
                uint32_t bd = stW + b_off + p * (16 * ROWB) + k16 * 32;
                ldm_x4(bW[p][0], bW[p][1], bW[p][2], bW[p][3], bd);
            }
#pragma unroll
            for (int mt = 0; mt < 2; mt++)
#pragma unroll
                for (int nt = 0; nt < 8; nt++)
                    mma_f16(acc[mt][nt], aA[mt], bW[nt >> 1][(nt & 1) * 2],
                            bW[nt >> 1][(nt & 1) * 2 + 1]);
        }
        __syncthreads();
        buf ^= 1;
    }

#pragma unroll
    for (int mt = 0; mt < 2; mt++) {
        int row_base = m0 + warp_m * 32 + mt * 16 + (lane >> 2);
#pragma unroll
        for (int half = 0; half < 2; half++) {
            int m = row_base + half * 8;
            int bidx = m / S;
            int sidx = m - bidx * S;
#pragma unroll
            for (int nt = 0; nt < 8; nt++) {
                int col = n0 + warp_n * 64 + nt * 8 + (lane & 3) * 2;
                float vx = acc[mt][nt][half * 2 + 0] + bias[col + 0];
                float vy = acc[mt][nt][half * 2 + 1] + bias[col + 1];
                if (MODE == 2) {
                    float2 v; v.x = vx; v.y = vy;
                    *((float2*)(C + (size_t)m * E_DIM + col)) = v;
                } else {
                    int hh = col >> 6;
                    int dd = col & 63;
                    size_t off = (((size_t)(bidx * N_HEADS + hh)) * S + sidx) * D_HEAD + dd;
                    *(__half2*)(Ch + off) = __floats2half2_rn(vx, vy);
                }
            }
        }
    }
}

// fused Q/K/V projection: blockIdx.y 0..15 -> Q, 16..47 -> K, 48..79 -> V
__global__ __launch_bounds__(256)
void qkv_gemm_kernel(const float* __restrict__ bq, const float* __restrict__ bk,
                     const float* __restrict__ bv) {
    extern __shared__ char sm[];
    int by = blockIdx.y;
    int n0 = blockIdx.x * 128;
    if (by < 16) {
        gemm_body<0>(g_q16, g_wq16, bq, nullptr, g_pq16, Q_LEN, by * 128, n0, sm);
    } else if (by < 48) {
        gemm_body<0>(g_k16, g_wk16, bk, nullptr, g_pk16, K_LEN, (by - 16) * 128, n0, sm);
    } else {
        gemm_body<0>(g_v16, g_wv16, bv, nullptr, g_pv16, K_LEN, (by - 48) * 128, n0, sm);
    }
}

// O projection: fp32 out
__global__ __launch_bounds__(256)
void o_gemm_kernel(const float* __restrict__ bo, float* __restrict__ out) {
    extern __shared__ char sm[];
    gemm_body<2>(g_ao16, g_wo16, bo, out, nullptr, Q_LEN,
                 blockIdx.y * 128, blockIdx.x * 128, sm);
}

// ---------------- HMMA flash attention, fp16, 64-row Q tiles ----------------
#define AROW    144                   // bytes per 64-elem fp16 row (+16 pad)
#define Q_BYTES (64 * AROW)           // 9216
#define KV_TILE (64 * AROW)           // 9216
#define KV_STG  (2 * KV_TILE)         // K, V = 18432
#define AT_Q    0
#define AT_KV   Q_BYTES               // 9216
#define AT_MS   (AT_KV + 2 * KV_STG)  // 46080
#define AT_SMEM (AT_MS + K_LEN * 4)   // 54272

__global__ __launch_bounds__(128, 3)
void attention_tc_kernel(const __half* __restrict__ q_g,
                         const __half* __restrict__ k_g,
                         const __half* __restrict__ v_g,
                         __half* __restrict__ o_g) {
    extern __shared__ char sm[];
    uint32_t sbase = smem_u32(sm);
    int tid = threadIdx.x;
    int lane = tid & 31;
    int wid = tid >> 5;          // 0..3
    int qt = blockIdx.x;         // 0..15
    int h = blockIdx.y;
    int b = blockIdx.z;
    int bh = b * N_HEADS + h;

    // Q + mask loads
    {
#pragma unroll
        for (int i = 0; i < 4; i++) {
            int c = tid + i * 128;          // 0..511
            int row = c >> 3, seg = c & 7;
            uint32_t dst = sbase + AT_Q + row * AROW + seg * 16;
            CP_ASYNC16(dst, q_g + ((size_t)(bh * Q_LEN + qt * 64 + row)) * 64 + seg * 8);
        }
        const float* msrc = g_maskf + b * K_LEN;
#pragma unroll
        for (int i = 0; i < 4; i++) {
            int c = tid + i * 128;          // 0..511
            CP_ASYNC16(sbase + AT_MS + c * 16, msrc + c * 4);
        }
    }
    CP_COMMIT();

    const __half* kvs[2] = {k_g, v_g};
    auto load_kv = [&](int buf, int kt) {
        uint32_t SB = sbase + AT_KV + buf * KV_STG;
#pragma unroll
        for (int i = 0; i < 8; i++) {
            int c = tid + i * 128;          // 0..1023
            int t = c >> 9, rem = c & 511;
            int row = rem >> 3, seg = rem & 7;
            CP_ASYNC16(SB + t * KV_TILE + row * AROW + seg * 16,
                       kvs[t] + ((size_t)(bh * K_LEN + kt * 64 + row)) * 64 + seg * 8);
        }
    };
    load_kv(0, 0);
    CP_COMMIT();
    CP_WAIT(1);            // Q + mask complete
    __syncthreads();

    // Q fragments (register resident for whole kernel)
    uint32_t qf[4][4];
    {
        uint32_t qaddr = sbase + AT_Q + (wid * 16 + (lane & 15)) * AROW + (lane >> 4) * 16;
#pragma unroll
        for (int c2 = 0; c2 < 4; c2++)
            ldm_x4(qf[c2][0], qf[c2][1], qf[c2][2], qf[c2][3], qaddr + c2 * 32);
    }

    float oacc[8][4];
#pragma unroll
    for (int i = 0; i < 8; i++)
#pragma unroll
        for (int j = 0; j < 4; j++) oacc[i][j] = 0.0f;
    float m0 = -50000.0f, m1 = -50000.0f, l0 = 0.0f, l1 = 0.0f;

    for (int kt = 0; kt < K_LEN / 64; kt++) {
        int buf = kt & 1;
        if (kt + 1 < K_LEN / 64) {
            load_kv(buf ^ 1, kt + 1);
            CP_COMMIT();
            CP_WAIT(1);
        } else {
            CP_WAIT(0);
        }
        __syncthreads();

        uint32_t SB = sbase + AT_KV + buf * KV_STG;

        // S = Q K^T, fp32 accum
        float sacc[8][4];
#pragma unroll
        for (int i = 0; i < 8; i++)
#pragma unroll
            for (int j = 0; j < 4; j++) sacc[i][j] = 0.0f;
#pragma unroll
        for (int c2 = 0; c2 < 4; c2++) {
            uint32_t kf[4][4];
#pragma unroll
            for (int p = 0; p < 4; p++) {
                uint32_t kaddr = SB + (uint32_t)((p * 16 + (lane >> 4) * 8 + (lane & 7)) * AROW
                               + ((lane >> 3) & 1) * 16 + c2 * 32);
                ldm_x4(kf[p][0], kf[p][1], kf[p][2], kf[p][3], kaddr);
            }
#pragma unroll
            for (int nt = 0; nt < 8; nt++)
                mma_f16(sacc[nt], qf[c2], kf[nt >> 1][(nt & 1) * 2],
                        kf[nt >> 1][(nt & 1) * 2 + 1]);
        }

        // scale to log2 domain + mask
        const float* msp = (const float*)(sm + AT_MS) + kt * 64;
#pragma unroll
        for (int nt = 0; nt < 8; nt++) {
            float2 mv = *(const float2*)(msp + nt * 8 + (lane & 3) * 2);
            sacc[nt][0] = fmaf(sacc[nt][0], SC_LOG2, mv.x);
            sacc[nt][1] = fmaf(sacc[nt][1], SC_LOG2, mv.y);
            sacc[nt][2] = fmaf(sacc[nt][2], SC_LOG2, mv.x);
            sacc[nt][3] = fmaf(sacc[nt][3], SC_LOG2, mv.y);
        }

        // online softmax (rows r0 = lane>>2, r1 = r0+8)
        float mx0 = sacc[0][0], mx1 = sacc[0][2];
#pragma unroll
        for (int nt = 0; nt < 8; nt++) {
            mx0 = fmaxf(mx0, fmaxf(sacc[nt][0], sacc[nt][1]));
            mx1 = fmaxf(mx1, fmaxf(sacc[nt][2], sacc[nt][3]));
        }
        mx0 = fmaxf(mx0, __shfl_xor_sync(0xffffffffu, mx0, 1));
        mx0 = fmaxf(mx0, __shfl_xor_sync(0xffffffffu, mx0, 2));
        mx1 = fmaxf(mx1, __shfl_xor_sync(0xffffffffu, mx1, 1));
        mx1 = fmaxf(mx1, __shfl_xor_sync(0xffffffffu, mx1, 2));
        float nm0 = fmaxf(m0, mx0), nm1 = fmaxf(m1, mx1);
        float a0 = ex2f(m0 - nm0), a1 = ex2f(m1 - nm1);
        m0 = nm0; m1 = nm1;

        float s0 = 0.0f, s1 = 0.0f;
#pragma unroll
        for (int nt = 0; nt < 8; nt++) {
            sacc[nt][0] = ex2f(sacc[nt][0] - nm0);
            sacc[nt][1] = ex2f(sacc[nt][1] - nm0);
            sacc[nt][2] = ex2f(sacc[nt][2] - nm1);
            sacc[nt][3] = ex2f(sacc[nt][3] - nm1);
            s0 += sacc[nt][0] + sacc[nt][1];
            s1 += sacc[nt][2] + sacc[nt][3];
        }
        s0 += __shfl_xor_sync(0xffffffffu, s0, 1);
        s0 += __shfl_xor_sync(0xffffffffu, s0, 2);
        s1 += __shfl_xor_sync(0xffffffffu, s1, 1);
        s1 += __shfl_xor_sync(0xffffffffu, s1, 2);
        l0 = l0 * a0 + s0;
        l1 = l1 * a1 + s1;
#pragma unroll
        for (int nf = 0; nf < 8; nf++) {
            oacc[nf][0] *= a0; oacc[nf][1] *= a0;
            oacc[nf][2] *= a1; oacc[nf][3] *= a1;
        }

        // O += P V (single pass)
#pragma unroll
        for (int j = 0; j < 4; j++) {
            uint32_t ph[4];
#pragma unroll
            for (int half = 0; half < 2; half++) {
                int f = 2 * j + half;
                // a0 = (r0, k 0-7), a1 = (r1, k 0-7), a2 = (r0, k 8-15), a3 = (r1, k 8-15)
                __half2 h01 = __floats2half2_rn(sacc[f][0], sacc[f][1]);
                __half2 h23 = __floats2half2_rn(sacc[f][2], sacc[f][3]);
                ph[half ? 2 : 0] = *(uint32_t*)&h01;
                ph[half ? 3 : 1] = *(uint32_t*)&h23;
            }
#pragma unroll
            for (int q2b = 0; q2b < 4; q2b++) {
                uint32_t vf[4];
                uint32_t vaddr = SB + KV_TILE
                               + (uint32_t)((j * 16 + (lane & 15)) * AROW
                               + q2b * 32 + (lane >> 4) * 16);
                ldm_x4t(vf[0], vf[1], vf[2], vf[3], vaddr);
                mma_f16(oacc[q2b * 2 + 0], ph, vf[0], vf[1]);
                mma_f16(oacc[q2b * 2 + 1], ph, vf[2], vf[3]);
            }
        }
        __syncthreads();
    }

    // epilogue: normalize, write fp16 [B*Q, E]
    float inv0 = 1.0f / l0, inv1 = 1.0f / l1;
    int qrow = qt * 64 + wid * 16 + (lane >> 2);
    size_t row0 = (size_t)b * Q_LEN + qrow;
    size_t row1 = row0 + 8;
#pragma unroll
    for (int nf = 0; nf < 8; nf++) {
        int col = h * 64 + nf * 8 + (lane & 3) * 2;
        *(__half2*)(o_g + row0 * E_DIM + col) =
            __floats2half2_rn(oacc[nf][0] * inv0, oacc[nf][1] * inv0);
        *(__half2*)(o_g + row1 * E_DIM + col) =
            __floats2half2_rn(oacc[nf][2] * inv1, oacc[nf][3] * inv1);
    }
}

// ---------------- launch ----------------
extern "C" void kernel_launch(void* const* d_in, const int* in_sizes, int n_in,
                              void* d_out, int out_size) {
    const float* query = (const float*)d_in[0];
    const float* key   = (const float*)d_in[1];
    const float* value = (const float*)d_in[2];
    const unsigned char* mask = (const unsigned char*)d_in[3];
    const float* Wq = (const float*)d_in[4];
    const float* bq = (const float*)d_in[5];
    const float* Wk = (const float*)d_in[6];
    const float* bk = (const float*)d_in[7];
    const float* Wv = (const float*)d_in[8];
    const float* bv = (const float*)d_in[9];
    const float* Wo = (const float*)d_in[10];
    const float* bo = (const float*)d_in[11];
    float* out = (float*)d_out;

    __half *pq16, *pk16, *pv16, *ao16;
    cudaGetSymbolAddress((void**)&pq16, g_pq16);
    cudaGetSymbolAddress((void**)&pk16, g_pk16);
    cudaGetSymbolAddress((void**)&pv16, g_pv16);
    cudaGetSymbolAddress((void**)&ao16, g_ao16);

    // 1: all converts + mask prep
    prep_kernel<<<dim3(192, 8), 256>>>(query, key, value, Wq, Wk, Wv, Wo, mask);

    // 2: fused Q/K/V projection GEMMs
    cudaFuncSetAttribute(qkv_gemm_kernel, cudaFuncAttributeMaxDynamicSharedMemorySize, GEMM_SMEM);
    qkv_gemm_kernel<<<dim3(8, 80), 256, GEMM_SMEM>>>(bq, bk, bv);

    // 3: attention
    cudaFuncSetAttribute(attention_tc_kernel, cudaFuncAttributeMaxDynamicSharedMemorySize, AT_SMEM);
    attention_tc_kernel<<<dim3(Q_LEN / 64, N_HEADS, B_SZ), 128, AT_SMEM>>>(
        pq16, pk16, pv16, ao16);

    // 4: O projection
    cudaFuncSetAttribute(o_gemm_kernel, cudaFuncAttributeMaxDynamicSharedMemorySize, GEMM_SMEM);
    o_gemm_kernel<<<dim3(8, 16), 256, GEMM_SMEM>>>(bo, out);
}

// round 9
// speedup vs baseline: 7.8508x; 1.1940x over previous
#include <cuda_runtime.h>
#include <cuda_fp16.h>
#include <cstdint>

#define B_SZ    2
#define Q_LEN   1024
#define K_LEN   2048
#define E_DIM   1024
#define N_HEADS 16
#define D_HEAD  64
// 0.125 * log2(e)
#define SC_LOG2 0.1803368801111204f

// ---------------- scratch (static device globals; no allocation) ----------------
__device__ __align__(16) __half g_q16[B_SZ * Q_LEN * E_DIM];
__device__ __align__(16) __half g_k16c[B_SZ * K_LEN * E_DIM];   // compacted key fp16
__device__ __align__(16) __half g_v16c[B_SZ * K_LEN * E_DIM];   // compacted value fp16
__device__ __align__(16) __half g_wq16[E_DIM * E_DIM];
__device__ __align__(16) __half g_wk16[E_DIM * E_DIM];
__device__ __align__(16) __half g_wv16[E_DIM * E_DIM];
__device__ __align__(16) __half g_wo16[E_DIM * E_DIM];
__device__ __align__(16) __half g_pq16[B_SZ * N_HEADS * Q_LEN * D_HEAD];
__device__ __align__(16) __half g_pk16[B_SZ * N_HEADS * K_LEN * D_HEAD];
__device__ __align__(16) __half g_pv16[B_SZ * N_HEADS * K_LEN * D_HEAD];
__device__ __align__(16) __half g_ao16[B_SZ * Q_LEN * E_DIM];

// compaction metadata
__device__ __align__(16) int   g_cidx[B_SZ * K_LEN];   // compacted j -> original position
__device__ __align__(16) int   g_ncomp[B_SZ];          // # unmasked keys
__device__ __align__(16) int   g_np128[B_SZ];          // padded to 128
__device__ __align__(16) int   g_ktcnt[B_SZ];          // np128 / 64
__device__ __align__(16) float g_cmask[B_SZ * K_LEN];  // 0 for real rows, -1e30 for pads

// ---------------- PTX helpers (portable sm_80+ only) ----------------
__device__ __forceinline__ uint32_t smem_u32(const void* p) {
    uint32_t a;
    asm("{ .reg .u64 t; cvta.to.shared.u64 t, %1; cvt.u32.u64 %0, t; }" : "=r"(a) : "l"(p));
    return a;
}
#define CP_ASYNC16(dst, src) \
    asm volatile("cp.async.cg.shared.global [%0], [%1], 16;" :: "r"(dst), "l"(src))
#define CP_COMMIT() asm volatile("cp.async.commit_group;" ::: "memory")
#define CP_WAIT(N)  asm volatile("cp.async.wait_group %0;" :: "n"(N) : "memory")

__device__ __forceinline__ void ldm_x4(uint32_t& r0, uint32_t& r1, uint32_t& r2,
                                       uint32_t& r3, uint32_t addr) {
    asm volatile("ldmatrix.sync.aligned.m8n8.x4.shared.b16 {%0,%1,%2,%3}, [%4];"
                 : "=r"(r0), "=r"(r1), "=r"(r2), "=r"(r3) : "r"(addr));
}
__device__ __forceinline__ void ldm_x4t(uint32_t& r0, uint32_t& r1, uint32_t& r2,
                                        uint32_t& r3, uint32_t addr) {
    asm volatile("ldmatrix.sync.aligned.m8n8.x4.trans.shared.b16 {%0,%1,%2,%3}, [%4];"
                 : "=r"(r0), "=r"(r1), "=r"(r2), "=r"(r3) : "r"(addr));
}
__device__ __forceinline__ void mma_f16(float* c, const uint32_t* a,
                                        uint32_t b0, uint32_t b1) {
    asm volatile(
        "mma.sync.aligned.m16n8k16.row.col.f32.f16.f16.f32 "
        "{%0,%1,%2,%3}, {%4,%5,%6,%7}, {%8,%9}, {%0,%1,%2,%3};"
        : "+f"(c[0]), "+f"(c[1]), "+f"(c[2]), "+f"(c[3])
        : "r"(a[0]), "r"(a[1]), "r"(a[2]), "r"(a[3]), "r"(b0), "r"(b1));
}
__device__ __forceinline__ float ex2f(float x) {
    float y; asm("ex2.approx.ftz.f32 %0, %1;" : "=f"(y) : "f"(x)); return y;
}

// ---------------- prep: converts + mask scan/compaction metadata ----------------
// blockIdx.y: 0=query, 1..4=Wq/Wk/Wv/Wo, 5=mask scan (block x 0 only)
__global__ __launch_bounds__(256)
void prep_kernel(const float* __restrict__ q,
                 const float* __restrict__ wq, const float* __restrict__ wk,
                 const float* __restrict__ wv, const float* __restrict__ wo,
                 const unsigned char* __restrict__ mask) {
    int task = blockIdx.y;
    int tid = threadIdx.x;
    if (task == 5) {
        if (blockIdx.x != 0) return;
        const int NM = B_SZ * K_LEN;
        // dtype sniff
        int gt1 = 0, off = 0, low = 0;
        for (int i = tid; i < NM; i += 256) {
            unsigned char c = mask[i];
            if (c > 1) gt1 = 1;
            if ((i & 3) != 0 && c != 0) off = 1;
            if ((i & 3) == 0 && c != 0) low = 1;
        }
        int any_gt1 = __syncthreads_or(gt1);
        int any_off = __syncthreads_or(off);
        int any_low = __syncthreads_or(low);
        // warp 0/1: ballot prefix-scan for batch 0/1
        __shared__ int s_n[B_SZ];
        int w = tid >> 5, lane = tid & 31;
        if (w < B_SZ) {
            int cnt = 0;
            for (int c = 0; c < K_LEN / 32; c++) {
                int i = c * 32 + lane;
                int gi = w * K_LEN + i;
                bool mval;
                if (any_gt1) {
                    if (any_low) mval = (((const unsigned short*)mask)[gi] != 0);
                    else         mval = (((const float*)mask)[gi] != 0.0f);
                } else {
                    if (any_off) mval = (mask[gi] != 0);
                    else         mval = (((const int*)mask)[gi] != 0);
                }
                bool valid = !mval;
                unsigned bal = __ballot_sync(0xffffffffu, valid);
                if (valid)
                    g_cidx[w * K_LEN + cnt + __popc(bal & ((1u << lane) - 1))] = i;
                cnt += __popc(bal);
            }
            if (lane == 0) {
                s_n[w] = cnt;
                g_ncomp[w] = cnt;
                int np = (cnt + 127) & ~127;
                g_np128[w] = np;
                g_ktcnt[w] = np >> 6;
            }
        }
        __syncthreads();
        for (int i = tid; i < B_SZ * K_LEN; i += 256) {
            int bb = i >> 11;          // / K_LEN
            int jp = i & (K_LEN - 1);
            g_cmask[i] = (jp < s_n[bb]) ? 0.0f : -1e30f;
        }
        return;
    }
    const float* srcs[5] = {q, wq, wk, wv, wo};
    __half* dsts[5] = {g_q16, g_wq16, g_wk16, g_wv16, g_wo16};
    const int n4s[5] = {(B_SZ * Q_LEN * E_DIM) / 4, (E_DIM * E_DIM) / 4,
                        (E_DIM * E_DIM) / 4, (E_DIM * E_DIM) / 4, (E_DIM * E_DIM) / 4};
    const float* x = srcs[task];
    __half* o = dsts[task];
    int n4 = n4s[task];
    int i = blockIdx.x * 256 + threadIdx.x;
    int stride = gridDim.x * 256;
    for (; i < n4; i += stride) {
        float4 vv = ((const float4*)x)[i];
        ((__half2*)o)[i * 2 + 0] = __floats2half2_rn(vv.x, vv.y);
        ((__half2*)o)[i * 2 + 1] = __floats2half2_rn(vv.z, vv.w);
    }
}

// ---------------- gather: compact key/value rows + fp32->fp16 ----------------
// block handles 8 compacted rows; grid (K_LEN/8, B_SZ)
__global__ __launch_bounds__(256)
void gather_kernel(const float* __restrict__ key, const float* __restrict__ value) {
    int b = blockIdx.y;
    int np = g_np128[b];
    int j0 = blockIdx.x * 8;
    if (j0 >= np) return;
    int n = g_ncomp[b];
    int tid = threadIdx.x;
    int r = tid >> 5, lane = tid & 31;
    int j = j0 + r;
    if (j >= np) return;
    size_t dst = ((size_t)b * K_LEN + j) * E_DIM;
    __half2* kd = (__half2*)(g_k16c + dst);
    __half2* vd = (__half2*)(g_v16c + dst);
    if (j < n) {
        int src = g_cidx[b * K_LEN + j];
        const float4* ks = (const float4*)(key   + ((size_t)b * K_LEN + src) * E_DIM);
        const float4* vs = (const float4*)(value + ((size_t)b * K_LEN + src) * E_DIM);
#pragma unroll
        for (int u = 0; u < 8; u++) {
            int e4 = lane + u * 32;
            float4 kv = ks[e4];
            float4 vv = vs[e4];
            kd[e4 * 2 + 0] = __floats2half2_rn(kv.x, kv.y);
            kd[e4 * 2 + 1] = __floats2half2_rn(kv.z, kv.w);
            vd[e4 * 2 + 0] = __floats2half2_rn(vv.x, vv.y);
            vd[e4 * 2 + 1] = __floats2half2_rn(vv.z, vv.w);
        }
    } else {
        __half2 z = __floats2half2_rn(0.0f, 0.0f);
#pragma unroll
        for (int u = 0; u < 8; u++) {
            int e4 = lane + u * 32;
            kd[e4 * 2 + 0] = z; kd[e4 * 2 + 1] = z;
            vd[e4 * 2 + 0] = z; vd[e4 * 2 + 1] = z;
        }
    }
}

// ---------------- HMMA fp16 GEMM common body ----------------
#define KSTAGE     32
#define ROWB       80
#define TILE_B     (128 * ROWB)
#define STAGE_B    (2 * TILE_B)          // A, W
#define GEMM_SMEM  (2 * STAGE_B)         // 40960

// MODE 0: fp16 out scattered [B,H,S,D]; MODE 2: fp32 [M,N]
template <int MODE>
__device__ __forceinline__
void gemm_body(const __half* __restrict__ A16, const __half* __restrict__ W16,
               const float* __restrict__ bias, float* __restrict__ C,
               __half* __restrict__ Ch, int S, int m0, int n0, char* sm) {
    uint32_t sbase = smem_u32(sm);
    int tid = threadIdx.x;
    int wid = tid >> 5;
    int lane = tid & 31;
    int warp_m = wid & 3;
    int warp_n = wid >> 2;

    auto load_stage = [&](int buf, int kt) {
        uint32_t dst_base = sbase + buf * STAGE_B;
#pragma unroll
        for (int t = 0; t < 2; t++) {
            const __half* src = (t == 0 ? A16 + (size_t)m0 * E_DIM
                                        : W16 + (size_t)n0 * E_DIM) + kt * KSTAGE;
#pragma unroll
            for (int j = 0; j < 2; j++) {
                int s = tid + j * 256;
                int row = s >> 2;
                int c16 = s & 3;
                uint32_t dst = dst_base + t * TILE_B + row * ROWB + c16 * 16;
                CP_ASYNC16(dst, (const char*)(src + (size_t)row * E_DIM + c16 * 8));
            }
        }
    };

    uint32_t a_off = (uint32_t)((warp_m * 32 + (lane & 15)) * ROWB + (lane >> 4) * 16);
    uint32_t b_off = (uint32_t)((warp_n * 64 + ((lane >> 4) * 8) + (lane & 7)) * ROWB
                                + ((lane >> 3) & 1) * 16);

    float acc[2][8][4];
#pragma unroll
    for (int i = 0; i < 2; i++)
#pragma unroll
        for (int j = 0; j < 8; j++)
#pragma unroll
            for (int kk = 0; kk < 4; kk++) acc[i][j][kk] = 0.0f;

    load_stage(0, 0);
    CP_COMMIT();

    int buf = 0;
    for (int kt = 0; kt < E_DIM / KSTAGE; kt++) {
        if (kt + 1 < E_DIM / KSTAGE) {
            load_stage(buf ^ 1, kt + 1);
            CP_COMMIT();
            CP_WAIT(1);
        } else {
            CP_WAIT(0);
        }
        __syncthreads();

        uint32_t stA = sbase + buf * STAGE_B;
        uint32_t stW = stA + TILE_B;
#pragma unroll
        for (int k16 = 0; k16 < 2; k16++) {
            uint32_t aA[2][4], bW[4][4];
#pragma unroll
            for (int mt = 0; mt < 2; mt++) {
                uint32_t ad = stA + a_off + mt * (16 * ROWB) + k16 * 32;
                ldm_x4(aA[mt][0], aA[mt][1], aA[mt][2], aA[mt][3], ad);
            }
#pragma unroll
            for (int p = 0; p < 4; p++) {
                uint32_t bd = stW + b_off + p * (16 * ROWB) + k16 * 32;
                ldm_x4(bW[p][0], bW[p][1], bW[p][2], bW[p][3], bd);
            }
#pragma unroll
            for (int mt = 0; mt < 2; mt++)
#pragma unroll
                for (int nt = 0; nt < 8; nt++)
                    mma_f16(acc[mt][nt], aA[mt], bW[nt >> 1][(nt & 1) * 2],
                            bW[nt >> 1][(nt & 1) * 2 + 1]);
        }
        __syncthreads();
        buf ^= 1;
    }

#pragma unroll
    for (int mt = 0; mt < 2; mt++) {
        int row_base = m0 + warp_m * 32 + mt * 16 + (lane >> 2);
#pragma unroll
        for (int half = 0; half < 2; half++) {
            int m = row_base + half * 8;
            int bidx = m / S;
            int sidx = m - bidx * S;
#pragma unroll
            for (int nt = 0; nt < 8; nt++) {
                int col = n0 + warp_n * 64 + nt * 8 + (lane & 3) * 2;
                float vx = acc[mt][nt][half * 2 + 0] + bias[col + 0];
                float vy = acc[mt][nt][half * 2 + 1] + bias[col + 1];
                if (MODE == 2) {
                    float2 v; v.x = vx; v.y = vy;
                    *((float2*)(C + (size_t)m * E_DIM + col)) = v;
                } else {
                    int hh = col >> 6;
                    int dd = col & 63;
                    size_t off = (((size_t)(bidx * N_HEADS + hh)) * S + sidx) * D_HEAD + dd;
                    *(__half2*)(Ch + off) = __floats2half2_rn(vx, vy);
                }
            }
        }
    }
}

// fused Q/K/V projection: blockIdx.y 0..15 -> Q, 16..47 -> K, 48..79 -> V
// K/V tiles beyond the compacted row count exit immediately.
__global__ __launch_bounds__(256)
void qkv_gemm_kernel(const float* __restrict__ bq, const float* __restrict__ bk,
                     const float* __restrict__ bv) {
    extern __shared__ char sm[];
    int by = blockIdx.y;
    int n0 = blockIdx.x * 128;
    if (by < 16) {
        gemm_body<0>(g_q16, g_wq16, bq, nullptr, g_pq16, Q_LEN, by * 128, n0, sm);
    } else if (by < 48) {
        int t = by - 16;
        if (((t & 15) << 7) >= g_np128[t >> 4]) return;
        gemm_body<0>(g_k16c, g_wk16, bk, nullptr, g_pk16, K_LEN, t * 128, n0, sm);
    } else {
        int t = by - 48;
        if (((t & 15) << 7) >= g_np128[t >> 4]) return;
        gemm_body<0>(g_v16c, g_wv16, bv, nullptr, g_pv16, K_LEN, t * 128, n0, sm);
    }
}

// O projection: fp32 out
__global__ __launch_bounds__(256)
void o_gemm_kernel(const float* __restrict__ bo, float* __restrict__ out) {
    extern __shared__ char sm[];
    gemm_body<2>(g_ao16, g_wo16, bo, out, nullptr, Q_LEN,
                 blockIdx.y * 128, blockIdx.x * 128, sm);
}

// ---------------- HMMA flash attention, fp16, 64-row Q tiles, compacted K ----------
#define AROW    144                   // bytes per 64-elem fp16 row (+16 pad)
#define Q_BYTES (64 * AROW)           // 9216
#define KV_TILE (64 * AROW)           // 9216
#define KV_STG  (2 * KV_TILE)         // K, V = 18432
#define AT_Q    0
#define AT_KV   Q_BYTES               // 9216
#define AT_MS   (AT_KV + 2 * KV_STG)  // 46080
#define AT_SMEM (AT_MS + K_LEN * 4)   // 54272

__global__ __launch_bounds__(128, 3)
void attention_tc_kernel(const __half* __restrict__ q_g,
                         const __half* __restrict__ k_g,
                         const __half* __restrict__ v_g,
                         __half* __restrict__ o_g) {
    extern __shared__ char sm[];
    uint32_t sbase = smem_u32(sm);
    int tid = threadIdx.x;
    int lane = tid & 31;
    int wid = tid >> 5;          // 0..3
    int qt = blockIdx.x;         // 0..15
    int h = blockIdx.y;
    int b = blockIdx.z;
    int bh = b * N_HEADS + h;
    int ktc = g_ktcnt[b];        // compacted tile count (>=2, even)

    // Q + compacted-mask loads
    {
#pragma unroll
        for (int i = 0; i < 4; i++) {
            int c = tid + i * 128;          // 0..511
            int row = c >> 3, seg = c & 7;
            uint32_t dst = sbase + AT_Q + row * AROW + seg * 16;
            CP_ASYNC16(dst, q_g + ((size_t)(bh * Q_LEN + qt * 64 + row)) * 64 + seg * 8);
        }
        const float* msrc = g_cmask + b * K_LEN;
#pragma unroll
        for (int i = 0; i < 4; i++) {
            int c = tid + i * 128;          // 0..511
            CP_ASYNC16(sbase + AT_MS + c * 16, msrc + c * 4);
        }
    }
    CP_COMMIT();

    const __half* kvs[2] = {k_g, v_g};
    auto load_kv = [&](int buf, int kt) {
        uint32_t SB = sbase + AT_KV + buf * KV_STG;
#pragma unroll
        for (int i = 0; i < 8; i++) {
            int c = tid + i * 128;          // 0..1023
            int t = c >> 9, rem = c & 511;
            int row = rem >> 3, seg = rem & 7;
            CP_ASYNC16(SB + t * KV_TILE + row * AROW + seg * 16,
                       kvs[t] + ((size_t)(bh * K_LEN + kt * 64 + row)) * 64 + seg * 8);
        }
    };
    load_kv(0, 0);
    CP_COMMIT();
    CP_WAIT(1);            // Q + mask complete
    __syncthreads();

    // Q fragments (register resident for whole kernel)
    uint32_t qf[4][4];
    {
        uint32_t qaddr = sbase + AT_Q + (wid * 16 + (lane & 15)) * AROW + (lane >> 4) * 16;
#pragma unroll
        for (int c2 = 0; c2 < 4; c2++)
            ldm_x4(qf[c2][0], qf[c2][1], qf[c2][2], qf[c2][3], qaddr + c2 * 32);
    }

    float oacc[8][4];
#pragma unroll
    for (int i = 0; i < 8; i++)
#pragma unroll
        for (int j = 0; j < 4; j++) oacc[i][j] = 0.0f;
    float m0 = -50000.0f, m1 = -50000.0f, l0 = 0.0f, l1 = 0.0f;

    for (int kt = 0; kt < ktc; kt++) {
        int buf = kt & 1;
        if (kt + 1 < ktc) {
            load_kv(buf ^ 1, kt + 1);
            CP_COMMIT();
            CP_WAIT(1);
        } else {
            CP_WAIT(0);
        }
        __syncthreads();

        uint32_t SB = sbase + AT_KV + buf * KV_STG;

        // S = Q K^T, fp32 accum
        float sacc[8][4];
#pragma unroll
        for (int i = 0; i < 8; i++)
#pragma unroll
            for (int j = 0; j < 4; j++) sacc[i][j] = 0.0f;
#pragma unroll
        for (int c2 = 0; c2 < 4; c2++) {
            uint32_t kf[4][4];
#pragma unroll
            for (int p = 0; p < 4; p++) {
                uint32_t kaddr = SB + (uint32_t)((p * 16 + (lane >> 4) * 8 + (lane & 7)) * AROW
                               + ((lane >> 3) & 1) * 16 + c2 * 32);
                ldm_x4(kf[p][0], kf[p][1], kf[p][2], kf[p][3], kaddr);
            }
#pragma unroll
            for (int nt = 0; nt < 8; nt++)
                mma_f16(sacc[nt], qf[c2], kf[nt >> 1][(nt & 1) * 2],
                        kf[nt >> 1][(nt & 1) * 2 + 1]);
        }

        // scale to log2 domain + pad mask
        const float* msp = (const float*)(sm + AT_MS) + kt * 64;
#pragma unroll
        for (int nt = 0; nt < 8; nt++) {
            float2 mv = *(const float2*)(msp + nt * 8 + (lane & 3) * 2);
            sacc[nt][0] = fmaf(sacc[nt][0], SC_LOG2, mv.x);
            sacc[nt][1] = fmaf(sacc[nt][1], SC_LOG2, mv.y);
            sacc[nt][2] = fmaf(sacc[nt][2], SC_LOG2, mv.x);
            sacc[nt][3] = fmaf(sacc[nt][3], SC_LOG2, mv.y);
        }

        // online softmax (rows r0 = lane>>2, r1 = r0+8)
        float mx0 = sacc[0][0], mx1 = sacc[0][2];
#pragma unroll
        for (int nt = 0; nt < 8; nt++) {
            mx0 = fmaxf(mx0, fmaxf(sacc[nt][0], sacc[nt][1]));
            mx1 = fmaxf(mx1, fmaxf(sacc[nt][2], sacc[nt][3]));
        }
        mx0 = fmaxf(mx0, __shfl_xor_sync(0xffffffffu, mx0, 1));
        mx0 = fmaxf(mx0, __shfl_xor_sync(0xffffffffu, mx0, 2));
        mx1 = fmaxf(mx1, __shfl_xor_sync(0xffffffffu, mx1, 1));
        mx1 = fmaxf(mx1, __shfl_xor_sync(0xffffffffu, mx1, 2));
        float nm0 = fmaxf(m0, mx0), nm1 = fmaxf(m1, mx1);
        float a0 = ex2f(m0 - nm0), a1 = ex2f(m1 - nm1);
        m0 = nm0; m1 = nm1;

        float s0 = 0.0f, s1 = 0.0f;
#pragma unroll
        for (int nt = 0; nt < 8; nt++) {
            sacc[nt][0] = ex2f(sacc[nt][0] - nm0);
            sacc[nt][1] = ex2f(sacc[nt][1] - nm0);
            sacc[nt][2] = ex2f(sacc[nt][2] - nm1);
            sacc[nt][3] = ex2f(sacc[nt][3] - nm1);
            s0 += sacc[nt][0] + sacc[nt][1];
            s1 += sacc[nt][2] + sacc[nt][3];
        }
        s0 += __shfl_xor_sync(0xffffffffu, s0, 1);
        s0 += __shfl_xor_sync(0xffffffffu, s0, 2);
        s1 += __shfl_xor_sync(0xffffffffu, s1, 1);
        s1 += __shfl_xor_sync(0xffffffffu, s1, 2);
        l0 = l0 * a0 + s0;
        l1 = l1 * a1 + s1;
#pragma unroll
        for (int nf = 0; nf < 8; nf++) {
            oacc[nf][0] *= a0; oacc[nf][1] *= a0;
            oacc[nf][2] *= a1; oacc[nf][3] *= a1;
        }

        // O += P V (single pass)
#pragma unroll
        for (int j = 0; j < 4; j++) {
            uint32_t ph[4];
#pragma unroll
            for (int half = 0; half < 2; half++) {
                int f = 2 * j + half;
                // a0 = (r0, k 0-7), a1 = (r1, k 0-7), a2 = (r0, k 8-15), a3 = (r1, k 8-15)
                __half2 h01 = __floats2half2_rn(sacc[f][0], sacc[f][1]);
                __half2 h23 = __floats2half2_rn(sacc[f][2], sacc[f][3]);
                ph[half ? 2 : 0] = *(uint32_t*)&h01;
                ph[half ? 3 : 1] = *(uint32_t*)&h23;
            }
#pragma unroll
            for (int q2b = 0; q2b < 4; q2b++) {
                uint32_t vf[4];
                uint32_t vaddr = SB + KV_TILE
                               + (uint32_t)((j * 16 + (lane & 15)) * AROW
                               + q2b * 32 + (lane >> 4) * 16);
                ldm_x4t(vf[0], vf[1], vf[2], vf[3], vaddr);
                mma_f16(oacc[q2b * 2 + 0], ph, vf[0], vf[1]);
                mma_f16(oacc[q2b * 2 + 1], ph, vf[2], vf[3]);
            }
        }
        __syncthreads();
    }

    // epilogue: normalize, write fp16 [B*Q, E]
    float inv0 = 1.0f / l0, inv1 = 1.0f / l1;
    int qrow = qt * 64 + wid * 16 + (lane >> 2);
    size_t row0 = (size_t)b * Q_LEN + qrow;
    size_t row1 = row0 + 8;
#pragma unroll
    for (int nf = 0; nf < 8; nf++) {
        int col = h * 64 + nf * 8 + (lane & 3) * 2;
        *(__half2*)(o_g + row0 * E_DIM + col) =
            __floats2half2_rn(oacc[nf][0] * inv0, oacc[nf][1] * inv0);
        *(__half2*)(o_g + row1 * E_DIM + col) =
            __floats2half2_rn(oacc[nf][2] * inv1, oacc[nf][3] * inv1);
    }
}

// ---------------- launch ----------------
extern "C" void kernel_launch(void* const* d_in, const int* in_sizes, int n_in,
                              void* d_out, int out_size) {
    const float* query = (const float*)d_in[0];
    const float* key   = (const float*)d_in[1];
    const float* value = (const float*)d_in[2];
    const unsigned char* mask = (const unsigned char*)d_in[3];
    const float* Wq = (const float*)d_in[4];
    const float* bq = (const float*)d_in[5];
    const float* Wk = (const float*)d_in[6];
    const float* bk = (const float*)d_in[7];
    const float* Wv = (const float*)d_in[8];
    const float* bv = (const float*)d_in[9];
    const float* Wo = (const float*)d_in[10];
    const float* bo = (const float*)d_in[11];
    float* out = (float*)d_out;

    __half *pq16, *pk16, *pv16, *ao16;
    cudaGetSymbolAddress((void**)&pq16, g_pq16);
    cudaGetSymbolAddress((void**)&pk16, g_pk16);
    cudaGetSymbolAddress((void**)&pv16, g_pv16);
    cudaGetSymbolAddress((void**)&ao16, g_ao16);

    // 1: converts (query + weights) + mask scan/compaction metadata
    prep_kernel<<<dim3(192, 6), 256>>>(query, Wq, Wk, Wv, Wo, mask);

    // 2: compact + convert key/value rows
    gather_kernel<<<dim3(K_LEN / 8, B_SZ), 256>>>(key, value);

    // 3: fused Q/K/V projection GEMMs (K/V tiles early-exit past compacted count)
    cudaFuncSetAttribute(qkv_gemm_kernel, cudaFuncAttributeMaxDynamicSharedMemorySize, GEMM_SMEM);
    qkv_gemm_kernel<<<dim3(8, 80), 256, GEMM_SMEM>>>(bq, bk, bv);

    // 4: attention over compacted keys
    cudaFuncSetAttribute(attention_tc_kernel, cudaFuncAttributeMaxDynamicSharedMemorySize, AT_SMEM);
    attention_tc_kernel<<<dim3(Q_LEN / 64, N_HEADS, B_SZ), 128, AT_SMEM>>>(
        pq16, pk16, pv16, ao16);

    // 5: O projection
    cudaFuncSetAttribute(o_gemm_kernel, cudaFuncAttributeMaxDynamicSharedMemorySize, GEMM_SMEM);
    o_gemm_kernel<<<dim3(8, 16), 256, GEMM_SMEM>>>(bo, out);
}